// round 1
// baseline (speedup 1.0000x reference)
#include <cuda_runtime.h>

#define NN   50000
#define EE   800000
#define CC   128
#define OUTC 64
#define KK1  16
#define KK2  8
#define EPSF 1e-5f
#define NBLK 98   // ceil(NN/512)

// ---------------- scratch (device globals; no allocation) ----------------
__device__ float g_dinv[NN];
__device__ int   g_outdeg[NN];
__device__ int   g_indeg[NN];
__device__ int   g_rowptr[NN + 1];
__device__ int   g_fill[NN];
__device__ int   g_col[EE];
__device__ float g_w[EE];
__device__ float g_T[(size_t)KK1 * NN * CC];   // Chebyshev blocks, 410 MB
__device__ float g_acc[(size_t)NN * CC];       // GEMM output / pre-BN
__device__ float g_h[(size_t)NN * CC];         // layer-1 activations
__device__ float g_B23[KK2 * CC * CC];         // packed [W2|W3] -> 1024x128
__device__ float g_bnsum[CC];
__device__ float g_bnsq[CC];
__device__ float g_scale[CC];
__device__ float g_shift[CC];
__device__ int   g_bsums[NBLK];

// ---------------- setup kernels ----------------
__global__ void k_zero_prep() {
    int i = blockIdx.x * blockDim.x + threadIdx.x;
    if (i < NN) { g_outdeg[i] = 0; g_indeg[i] = 0; g_fill[i] = 0; }
}

__global__ void k_count(const int* __restrict__ src, const int* __restrict__ dst) {
    int e = blockIdx.x * blockDim.x + threadIdx.x;
    if (e < EE) {
        atomicAdd(&g_outdeg[src[e]], 1);
        atomicAdd(&g_indeg[dst[e]], 1);
    }
}

__global__ void k_dinv() {
    int i = blockIdx.x * blockDim.x + threadIdx.x;
    if (i < NN) {
        int d = g_outdeg[i];
        g_dinv[i] = (d > 0) ? rsqrtf((float)d) : 0.0f;
    }
}

// exclusive scan of g_indeg -> g_rowptr (3-phase)
__global__ void k_scan1() {
    __shared__ int s[512];
    int t = threadIdx.x;
    int i = blockIdx.x * 512 + t;
    int v = (i < NN) ? g_indeg[i] : 0;
    s[t] = v;
    __syncthreads();
    for (int off = 1; off < 512; off <<= 1) {
        int a = (t >= off) ? s[t - off] : 0;
        __syncthreads();
        s[t] += a;
        __syncthreads();
    }
    if (i < NN) g_rowptr[i] = s[t] - v;   // local exclusive
    if (t == 511) g_bsums[blockIdx.x] = s[511];
}

__global__ void k_scan2() {
    __shared__ int s[128];
    int t = threadIdx.x;
    int v = (t < NBLK) ? g_bsums[t] : 0;
    s[t] = v;
    __syncthreads();
    for (int off = 1; off < 128; off <<= 1) {
        int a = (t >= off) ? s[t - off] : 0;
        __syncthreads();
        s[t] += a;
        __syncthreads();
    }
    if (t < NBLK) g_bsums[t] = s[t] - v;  // exclusive block offsets
}

__global__ void k_scan3() {
    int i = blockIdx.x * blockDim.x + threadIdx.x;
    if (i < NN) g_rowptr[i] += g_bsums[i >> 9];
    if (i == 0) g_rowptr[NN] = EE;
}

__global__ void k_fill(const int* __restrict__ src, const int* __restrict__ dst) {
    int e = blockIdx.x * blockDim.x + threadIdx.x;
    if (e < EE) {
        int s = src[e], d = dst[e];
        int p = g_rowptr[d] + atomicAdd(&g_fill[d], 1);
        g_col[p] = s;
        g_w[p] = -g_dinv[s] * g_dinv[d];
    }
}

// ---------------- propagation (dst-CSR SpMM), one warp per node ----------------
// out[T,outk] = alpha * sum_e w_e * z[col_e]  ( - T[subk] if subk >= 0 )
__global__ void k_prop(int zk, int subk, int outk, float alpha,
                       const float* __restrict__ xext) {
    int gw = (blockIdx.x * blockDim.x + threadIdx.x) >> 5;
    int lane = threadIdx.x & 31;
    if (gw >= NN) return;
    const float* z = (zk < 0) ? xext : (g_T + (size_t)zk * NN * CC);
    int beg = g_rowptr[gw], end = g_rowptr[gw + 1];
    float4 acc = make_float4(0.f, 0.f, 0.f, 0.f);
    int co = lane << 2;
    for (int e = beg; e < end; e++) {
        int c = __ldg(&g_col[e]);
        float w = __ldg(&g_w[e]);
        float4 v = *(const float4*)(z + (size_t)c * CC + co);
        acc.x += w * v.x; acc.y += w * v.y;
        acc.z += w * v.z; acc.w += w * v.w;
    }
    size_t o = (size_t)gw * CC + co;
    float4 r;
    if (subk >= 0) {
        float4 s = *(const float4*)(g_T + (size_t)subk * NN * CC + o);
        r = make_float4(alpha * acc.x - s.x, alpha * acc.y - s.y,
                        alpha * acc.z - s.z, alpha * acc.w - s.w);
    } else {
        r = make_float4(alpha * acc.x, alpha * acc.y, alpha * acc.z, alpha * acc.w);
    }
    *(float4*)(g_T + (size_t)outk * NN * CC + o) = r;
}

__global__ void k_copyT0(const float* __restrict__ x, int use_h) {
    size_t i = (size_t)blockIdx.x * blockDim.x + threadIdx.x;
    if (i < (size_t)NN * CC / 4) {
        float4 v = use_h ? ((const float4*)g_h)[i] : ((const float4*)x)[i];
        ((float4*)g_T)[i] = v;
    }
}

// ---------------- GEMM: g_acc[NN x 128] = T (k-blocked, K = Ktiles*16) @ B ----------------
// BM=64 BN=128 BK=16, 256 threads, thread tile 8x4, double-buffered smem.
__global__ __launch_bounds__(256) void k_gemm(const float* __restrict__ Bext,
                                              int useB23, int Ktiles) {
    __shared__ float As[2][16][68];    // [k][m], padded stride
    __shared__ float Bs[2][16][128];
    const float* B = useB23 ? g_B23 : Bext;

    int tid = threadIdx.x;
    int m0 = blockIdx.x * 64;
    int tm = (tid >> 5) << 3;     // warp-uniform row offset 0..56
    int tn = (tid & 31) << 2;     // col offset 0..124
    int am = tid >> 2;            // A load row 0..63
    int ac = (tid & 3) << 2;      // A load col-in-tile 0,4,8,12
    int bk = tid >> 4;            // B load k-row 0..15
    int bn = (tid & 15) << 3;     // B load col 0..120
    int arow = m0 + am;

    float acc[8][4];
#pragma unroll
    for (int i = 0; i < 8; i++)
#pragma unroll
        for (int j = 0; j < 4; j++) acc[i][j] = 0.f;

    float4 a_reg, b_reg0, b_reg1;
    // prefetch tile 0
    {
        const float* Ap = g_T + (size_t)arow * CC + ac;   // kb=0, c0=0
        a_reg = (arow < NN) ? *(const float4*)Ap : make_float4(0, 0, 0, 0);
        const float* Bp = B + (size_t)bk * 128 + bn;
        b_reg0 = *(const float4*)Bp;
        b_reg1 = *(const float4*)(Bp + 4);
    }
    As[0][ac + 0][am] = a_reg.x; As[0][ac + 1][am] = a_reg.y;
    As[0][ac + 2][am] = a_reg.z; As[0][ac + 3][am] = a_reg.w;
    *(float4*)&Bs[0][bk][bn] = b_reg0;
    *(float4*)&Bs[0][bk][bn + 4] = b_reg1;
    __syncthreads();

    int cur = 0;
    for (int kt = 0; kt < Ktiles; kt++) {
        if (kt + 1 < Ktiles) {
            int kk = (kt + 1) << 4;
            int kb = kk >> 7, c0 = kk & 127;
            const float* Ap = g_T + (size_t)kb * NN * CC + (size_t)arow * CC + c0 + ac;
            a_reg = (arow < NN) ? *(const float4*)Ap : make_float4(0, 0, 0, 0);
            const float* Bp = B + (size_t)(kk + bk) * 128 + bn;
            b_reg0 = *(const float4*)Bp;
            b_reg1 = *(const float4*)(Bp + 4);
        }
#pragma unroll
        for (int k = 0; k < 16; k++) {
            float4 a0 = *(const float4*)&As[cur][k][tm];
            float4 a1 = *(const float4*)&As[cur][k][tm + 4];
            float4 bv = *(const float4*)&Bs[cur][k][tn];
            float av[8] = {a0.x, a0.y, a0.z, a0.w, a1.x, a1.y, a1.z, a1.w};
            float bvv[4] = {bv.x, bv.y, bv.z, bv.w};
#pragma unroll
            for (int i = 0; i < 8; i++)
#pragma unroll
                for (int j = 0; j < 4; j++) acc[i][j] += av[i] * bvv[j];
        }
        if (kt + 1 < Ktiles) {
            int nb = cur ^ 1;
            As[nb][ac + 0][am] = a_reg.x; As[nb][ac + 1][am] = a_reg.y;
            As[nb][ac + 2][am] = a_reg.z; As[nb][ac + 3][am] = a_reg.w;
            *(float4*)&Bs[nb][bk][bn] = b_reg0;
            *(float4*)&Bs[nb][bk][bn + 4] = b_reg1;
            __syncthreads();
            cur = nb;
        }
    }
#pragma unroll
    for (int i = 0; i < 8; i++) {
        int r = m0 + tm + i;
        if (r < NN)
            *(float4*)(g_acc + (size_t)r * CC + tn) =
                make_float4(acc[i][0], acc[i][1], acc[i][2], acc[i][3]);
    }
}

// ---------------- BN ----------------
__global__ void k_zero_bn() {
    if (threadIdx.x < CC) { g_bnsum[threadIdx.x] = 0.f; g_bnsq[threadIdx.x] = 0.f; }
}

__global__ void k_bnstat() {
    int c = threadIdx.x;
    float s = 0.f, q = 0.f;
    for (int r = blockIdx.x; r < NN; r += gridDim.x) {
        float v = g_acc[(size_t)r * CC + c];
        s += v; q += v * v;
    }
    atomicAdd(&g_bnsum[c], s);
    atomicAdd(&g_bnsq[c], q);
}

// scale/shift: y = x*scale + shift ; layer-2/3 splits channel space 64|64
__global__ void k_bnfinal(const float* __restrict__ gA, const float* __restrict__ bA,
                          const float* __restrict__ gB, const float* __restrict__ bB) {
    int c = threadIdx.x;
    if (c >= CC) return;
    float mu = g_bnsum[c] * (1.0f / NN);
    float var = g_bnsq[c] * (1.0f / NN) - mu * mu;
    float gv, bv;
    if (gB != nullptr && c >= OUTC) { gv = gB[c - OUTC]; bv = bB[c - OUTC]; }
    else                            { gv = gA[c];        bv = bA[c]; }
    float sc = rsqrtf(var + EPSF) * gv;
    g_scale[c] = sc;
    g_shift[c] = bv - mu * sc;
}

__global__ void k_bnrelu() {
    size_t i = (size_t)blockIdx.x * blockDim.x + threadIdx.x;
    if (i < (size_t)NN * CC) {
        int c = (int)(i & 127);
        float v = g_acc[i] * g_scale[c] + g_shift[c];
        g_h[i] = fmaxf(v, 0.f);
    }
}

__global__ void k_out(float* __restrict__ out) {
    size_t i = (size_t)blockIdx.x * blockDim.x + threadIdx.x;
    if (i < (size_t)NN * CC) {
        int c = (int)(i & 127);
        size_t r = i >> 7;
        float v = g_acc[i] * g_scale[c] + g_shift[c];
        if (c < OUTC) out[r * OUTC + c] = v;
        else          out[(size_t)NN * OUTC + r * OUTC + (c - OUTC)] = v;
    }
}

// pack [W2|W3] -> g_B23 [1024 x 128]
__global__ void k_pack(const float* __restrict__ W2, const float* __restrict__ W3) {
    int i = blockIdx.x * blockDim.x + threadIdx.x;
    int tot = KK2 * CC * CC;
    if (i < tot) {
        int j = i & 127;
        int ki = i >> 7;           // k*128 + row
        g_B23[i] = (j < OUTC) ? W2[(size_t)ki * OUTC + j]
                              : W3[(size_t)ki * OUTC + (j - OUTC)];
    }
}

// ---------------- launcher ----------------
extern "C" void kernel_launch(void* const* d_in, const int* in_sizes, int n_in,
                              void* d_out, int out_size) {
    const float* x   = (const float*)d_in[0];
    const int*   ei  = (const int*)d_in[1];
    const float* W1  = (const float*)d_in[2];
    const float* g1  = (const float*)d_in[4];
    const float* be1 = (const float*)d_in[5];
    const float* W2  = (const float*)d_in[6];
    const float* g2  = (const float*)d_in[8];
    const float* be2 = (const float*)d_in[9];
    const float* W3  = (const float*)d_in[10];
    const float* g3  = (const float*)d_in[12];
    const float* be3 = (const float*)d_in[13];
    const int* src = ei;
    const int* dst = ei + EE;
    float* out = (float*)d_out;

    const int NB_N = (NN + 255) / 256;
    const int NB_E = (EE + 255) / 256;
    const int NB_PROP = (NN * 32 + 255) / 256;       // 6250
    const int NB_ELT = (NN * CC + 255) / 256;        // 25000
    const int NB_GEMM = (NN + 63) / 64;              // 782

    // graph preprocessing (CSR by dst + edge weights)
    k_zero_prep<<<NB_N, 256>>>();
    k_count<<<NB_E, 256>>>(src, dst);
    k_dinv<<<NB_N, 256>>>();
    k_scan1<<<NBLK, 512>>>();
    k_scan2<<<1, 128>>>();
    k_scan3<<<NB_N, 256>>>();
    k_fill<<<NB_E, 256>>>(src, dst);

    // ---- layer 1: Chebyshev K=16 on x ----
    k_copyT0<<<NB_PROP, 256>>>(x, 0);                      // T0 = x
    k_prop<<<NB_PROP, 256>>>(-1, -1, 1, 1.0f, x);          // T1 = L x
    for (int k = 2; k < KK1; k++)
        k_prop<<<NB_PROP, 256>>>(k - 1, k - 2, k, 2.0f, nullptr);
    k_gemm<<<NB_GEMM, 256>>>(W1, 0, KK1 * 8);              // acc = sum_k T_k W1_k
    k_zero_bn<<<1, 128>>>();
    k_bnstat<<<256, 128>>>();
    k_bnfinal<<<1, 128>>>(g1, be1, nullptr, nullptr);
    k_bnrelu<<<NB_ELT, 256>>>();                           // h = relu(BN(acc))

    // ---- layers 2+3 share propagations of h ----
    k_copyT0<<<NB_PROP, 256>>>(nullptr, 1);                // T0 = h
    k_prop<<<NB_PROP, 256>>>(0, -1, 1, 1.0f, nullptr);     // T1 = L h
    for (int k = 2; k < KK2; k++)
        k_prop<<<NB_PROP, 256>>>(k - 1, k - 2, k, 2.0f, nullptr);
    k_pack<<<(KK2 * CC * CC + 255) / 256, 256>>>(W2, W3);
    k_gemm<<<NB_GEMM, 256>>>(nullptr, 1, KK2 * 8);         // acc = [mu_raw | logstd_raw]
    k_zero_bn<<<1, 128>>>();
    k_bnstat<<<256, 128>>>();
    k_bnfinal<<<1, 128>>>(g2, be2, g3, be3);
    k_out<<<NB_ELT, 256>>>(out);
}

// round 6
// speedup vs baseline: 1.2482x; 1.2482x over previous
#include <cuda_runtime.h>
#include <cuda_bf16.h>
#include <cstdint>

#define NN   50000
#define EE   800000
#define CC   128
#define OUTC 64
#define KK1  16
#define KK2  8
#define EPSF 1e-5f
#define NBLK 98      // ceil(NN/512)

// ---------------- scratch (device globals; no allocation) ----------------
__device__ float g_dinv[NN];
__device__ int   g_outdeg[NN];
__device__ int   g_indeg[NN];
__device__ int   g_rowptr[NN + 1];
__device__ int   g_fill[NN];
__device__ int   g_col[EE];
__device__ float g_w[EE];
__device__ float g_T[(size_t)KK1 * NN * CC];        // fp32 Chebyshev blocks (410 MB)
__device__ float g_acc[(size_t)NN * CC];            // GEMM output / pre-BN
__device__ float g_h[(size_t)NN * CC];              // layer-1 activations
__device__ __nv_bfloat16 g_Whi1[CC * (KK1 * CC)];   // [n=128][k=2048]
__device__ __nv_bfloat16 g_Wlo1[CC * (KK1 * CC)];
__device__ __nv_bfloat16 g_Whi23[CC * (KK2 * CC)];  // [n=128][k=1024], packed [W2|W3]
__device__ __nv_bfloat16 g_Wlo23[CC * (KK2 * CC)];
__device__ float g_bnsum[CC];
__device__ float g_bnsq[CC];
__device__ float g_scale[CC];
__device__ float g_shift[CC];
__device__ int   g_bsums[NBLK];

// ---------------- PTX helpers (sm_80+ baseline features only) ----------------
__device__ __forceinline__ uint32_t smem_u32(const void* p) {
    uint32_t a;
    asm("{ .reg .u64 t; cvta.to.shared.u64 t, %1; cvt.u32.u64 %0, t; }" : "=r"(a) : "l"(p));
    return a;
}

#define LDSM_X4(r0, r1, r2, r3, addr)                                     \
    asm volatile("ldmatrix.sync.aligned.m8n8.x4.shared.b16 {%0,%1,%2,%3}, [%4];" \
        : "=r"(r0), "=r"(r1), "=r"(r2), "=r"(r3) : "r"(addr))

#define MMA_BF16(d, a, b0, b1)                                            \
    asm volatile("mma.sync.aligned.m16n8k16.row.col.f32.bf16.bf16.f32 "   \
        "{%0,%1,%2,%3}, {%4,%5,%6,%7}, {%8,%9}, {%0,%1,%2,%3};"           \
        : "+f"((d)[0]), "+f"((d)[1]), "+f"((d)[2]), "+f"((d)[3])          \
        : "r"((a)[0]), "r"((a)[1]), "r"((a)[2]), "r"((a)[3]),             \
          "r"(b0), "r"(b1))

// ---------------- setup kernels ----------------
__global__ void k_zero_prep() {
    int i = blockIdx.x * blockDim.x + threadIdx.x;
    if (i < NN) { g_outdeg[i] = 0; g_indeg[i] = 0; g_fill[i] = 0; }
}

__global__ void k_count(const int* __restrict__ src, const int* __restrict__ dst) {
    int e = blockIdx.x * blockDim.x + threadIdx.x;
    if (e < EE) {
        atomicAdd(&g_outdeg[src[e]], 1);
        atomicAdd(&g_indeg[dst[e]], 1);
    }
}

__global__ void k_dinv() {
    int i = blockIdx.x * blockDim.x + threadIdx.x;
    if (i < NN) {
        int d = g_outdeg[i];
        g_dinv[i] = (d > 0) ? rsqrtf((float)d) : 0.0f;
    }
}

__global__ void k_scan1() {
    __shared__ int s[512];
    int t = threadIdx.x;
    int i = blockIdx.x * 512 + t;
    int v = (i < NN) ? g_indeg[i] : 0;
    s[t] = v;
    __syncthreads();
    for (int off = 1; off < 512; off <<= 1) {
        int a = (t >= off) ? s[t - off] : 0;
        __syncthreads();
        s[t] += a;
        __syncthreads();
    }
    if (i < NN) g_rowptr[i] = s[t] - v;
    if (t == 511) g_bsums[blockIdx.x] = s[511];
}

__global__ void k_scan2() {
    __shared__ int s[128];
    int t = threadIdx.x;
    int v = (t < NBLK) ? g_bsums[t] : 0;
    s[t] = v;
    __syncthreads();
    for (int off = 1; off < 128; off <<= 1) {
        int a = (t >= off) ? s[t - off] : 0;
        __syncthreads();
        s[t] += a;
        __syncthreads();
    }
    if (t < NBLK) g_bsums[t] = s[t] - v;
}

__global__ void k_scan3() {
    int i = blockIdx.x * blockDim.x + threadIdx.x;
    if (i < NN) g_rowptr[i] += g_bsums[i >> 9];
    if (i == 0) g_rowptr[NN] = EE;
}

__global__ void k_fill(const int* __restrict__ src, const int* __restrict__ dst) {
    int e = blockIdx.x * blockDim.x + threadIdx.x;
    if (e < EE) {
        int s = src[e], d = dst[e];
        int p = g_rowptr[d] + atomicAdd(&g_fill[d], 1);
        g_col[p] = s;
        g_w[p] = -g_dinv[s] * g_dinv[d];
    }
}

// ---------------- propagation (dst-CSR SpMM), one warp per node ----------------
__global__ void k_prop(int zk, int subk, int outk, float alpha,
                       const float* __restrict__ xext) {
    int gw = (blockIdx.x * blockDim.x + threadIdx.x) >> 5;
    int lane = threadIdx.x & 31;
    if (gw >= NN) return;
    const float* z = (zk < 0) ? xext : (g_T + (size_t)zk * NN * CC);
    int beg = g_rowptr[gw], end = g_rowptr[gw + 1];
    float4 acc = make_float4(0.f, 0.f, 0.f, 0.f);
    int co = lane << 2;
    for (int e = beg; e < end; e++) {
        int c = __ldg(&g_col[e]);
        float w = __ldg(&g_w[e]);
        float4 v = *(const float4*)(z + (size_t)c * CC + co);
        acc.x += w * v.x; acc.y += w * v.y;
        acc.z += w * v.z; acc.w += w * v.w;
    }
    size_t o = (size_t)gw * CC + co;
    float4 r;
    if (subk >= 0) {
        float4 s = *(const float4*)(g_T + (size_t)subk * NN * CC + o);
        r = make_float4(alpha * acc.x - s.x, alpha * acc.y - s.y,
                        alpha * acc.z - s.z, alpha * acc.w - s.w);
    } else {
        r = make_float4(alpha * acc.x, alpha * acc.y, alpha * acc.z, alpha * acc.w);
    }
    *(float4*)(g_T + (size_t)outk * NN * CC + o) = r;
}

__global__ void k_copyT0(const float* __restrict__ x, int use_h) {
    size_t i = (size_t)blockIdx.x * blockDim.x + threadIdx.x;
    if (i < (size_t)NN * CC / 4) {
        float4 v = use_h ? ((const float4*)g_h)[i] : ((const float4*)x)[i];
        ((float4*)g_T)[i] = v;
    }
}

// ---------------- weight pack: fp32 [K][N] -> bf16 hi/lo [N][K] ----------------
__global__ void k_packW1(const float* __restrict__ W1) {
    int i = blockIdx.x * blockDim.x + threadIdx.x;
    if (i < KK1 * CC * CC) {
        int kk = i >> 7, n = i & 127;
        float v = W1[i];
        __nv_bfloat16 h = __float2bfloat16(v);
        g_Whi1[(size_t)n * (KK1 * CC) + kk] = h;
        g_Wlo1[(size_t)n * (KK1 * CC) + kk] = __float2bfloat16(v - __bfloat162float(h));
    }
}

__global__ void k_packW23(const float* __restrict__ W2, const float* __restrict__ W3) {
    int i = blockIdx.x * blockDim.x + threadIdx.x;
    if (i < KK2 * CC * CC) {
        int kk = i >> 7, n = i & 127;
        float v = (n < OUTC) ? W2[(size_t)kk * OUTC + n]
                             : W3[(size_t)kk * OUTC + (n - OUTC)];
        __nv_bfloat16 h = __float2bfloat16(v);
        g_Whi23[(size_t)n * (KK2 * CC) + kk] = h;
        g_Wlo23[(size_t)n * (KK2 * CC) + kk] = __float2bfloat16(v - __bfloat162float(h));
    }
}

// ---------------- mma.sync GEMM: g_acc[NN x 128] = T @ W (3-term bf16 split) ----------------
// BM=128, BN=128, BK=32. 256 threads = 8 warps (4m x 2n), warp tile 32x64.
// A loaded fp32 from g_T, split hi/lo in registers; B (weights) selected by flag
// INSIDE device code (host code must never take a __device__ symbol's address).
#define ROWB   80                  // smem row stride bytes (32 bf16 + 16B pad)
#define TILE_B (128 * ROWB)        // 10240 per tile

__device__ __forceinline__ uint32_t pack2(float a, float b) {
    __nv_bfloat162 t = __floats2bfloat162_rn(a, b);
    return *reinterpret_cast<uint32_t*>(&t);
}
__device__ __forceinline__ float resid(float v) {
    return v - __bfloat162float(__float2bfloat16(v));
}

__global__ __launch_bounds__(256) void k_mm(int which) {
    __shared__ __align__(16) char smem[4 * TILE_B];   // Ah | Al | Bh | Bl
    const __nv_bfloat16* __restrict__ Bhi = which ? g_Whi23 : g_Whi1;
    const __nv_bfloat16* __restrict__ Blo = which ? g_Wlo23 : g_Wlo1;
    const int Ktot = which ? (KK2 * CC) : (KK1 * CC);

    const uint32_t sm = smem_u32(smem);
    const uint32_t Ah = sm, Al = sm + TILE_B, Bh = sm + 2 * TILE_B, Bl = sm + 3 * TILE_B;
    const int tid = threadIdx.x;
    const int lane = tid & 31;
    const int w = tid >> 5;
    const int wm = w & 3;                 // m-warp 0..3 (32 rows each)
    const int wn = w >> 2;                // n-warp 0..1 (64 cols each)
    const int m0 = blockIdx.x * 128;
    const int NCH = Ktot >> 5;

    // copy mapping: row cr = tid>>1 (0..127), half cs = tid&1 (16 elems)
    const int cr = tid >> 1;
    const int cs = tid & 1;
    const int arow = m0 + cr;

    uint4 ah2[2], al2[2], bh2[2], bl2[2];   // staged chunk (16 bf16 each buffer)

    auto load_regs = [&](int c) {
        // A: 16 fp32 from g_T -> split
        float4 fa[4];
        if (arow < NN) {
            const float4* pa = (const float4*)(g_T +
                ((size_t)(c >> 2) * NN + arow) * CC + (c & 3) * 32 + cs * 16);
#pragma unroll
            for (int i = 0; i < 4; i++) fa[i] = pa[i];
        } else {
#pragma unroll
            for (int i = 0; i < 4; i++) fa[i] = make_float4(0.f, 0.f, 0.f, 0.f);
        }
#pragma unroll
        for (int i = 0; i < 2; i++) {
            float4 f0 = fa[2 * i], f1 = fa[2 * i + 1];
            ah2[i] = make_uint4(pack2(f0.x, f0.y), pack2(f0.z, f0.w),
                                pack2(f1.x, f1.y), pack2(f1.z, f1.w));
            al2[i] = make_uint4(pack2(resid(f0.x), resid(f0.y)),
                                pack2(resid(f0.z), resid(f0.w)),
                                pack2(resid(f1.x), resid(f1.y)),
                                pack2(resid(f1.z), resid(f1.w)));
        }
        // B: 16 bf16 hi + 16 lo (row cr of [N][K] weights)
        size_t gb = (size_t)cr * Ktot + c * 32 + cs * 16;
        const uint4* pw = (const uint4*)(Bhi + gb);
        const uint4* pl = (const uint4*)(Blo + gb);
        bh2[0] = pw[0]; bh2[1] = pw[1];
        bl2[0] = pl[0]; bl2[1] = pl[1];
    };

    float acc[2][8][4];
#pragma unroll
    for (int i = 0; i < 2; i++)
#pragma unroll
        for (int j = 0; j < 8; j++)
#pragma unroll
            for (int q = 0; q < 4; q++) acc[i][j][q] = 0.f;

    // lane-address components for ldmatrix
    const uint32_t a_row = wm * 32 + (lane & 15);
    const uint32_t a_k8  = (lane >> 4) << 3;
    const uint32_t b_row = wn * 64 + ((lane >> 4) << 3) + (lane & 7);
    const uint32_t b_k8  = ((lane >> 3) & 1) << 3;
    const uint32_t soff = (uint32_t)(cr * ROWB + cs * 32);

    // prologue: chunk 0 into smem
    load_regs(0);
    {
        *(uint4*)(smem + 0 * TILE_B + soff)      = ah2[0];
        *(uint4*)(smem + 0 * TILE_B + soff + 16) = ah2[1];
        *(uint4*)(smem + 1 * TILE_B + soff)      = al2[0];
        *(uint4*)(smem + 1 * TILE_B + soff + 16) = al2[1];
        *(uint4*)(smem + 2 * TILE_B + soff)      = bh2[0];
        *(uint4*)(smem + 2 * TILE_B + soff + 16) = bh2[1];
        *(uint4*)(smem + 3 * TILE_B + soff)      = bl2[0];
        *(uint4*)(smem + 3 * TILE_B + soff + 16) = bl2[1];
    }
    __syncthreads();

    for (int c = 0; c < NCH; c++) {
        if (c + 1 < NCH) load_regs(c + 1);   // LDG for next chunk in flight

#pragma unroll
        for (int ks = 0; ks < 2; ks++) {
            const uint32_t k0 = ks * 16;
            uint32_t ahf[2][4], alf[2][4];
#pragma unroll
            for (int mt = 0; mt < 2; mt++) {
                uint32_t addr = Ah + (a_row + mt * 16) * ROWB + (k0 + a_k8) * 2;
                LDSM_X4(ahf[mt][0], ahf[mt][1], ahf[mt][2], ahf[mt][3], addr);
                addr = Al + (a_row + mt * 16) * ROWB + (k0 + a_k8) * 2;
                LDSM_X4(alf[mt][0], alf[mt][1], alf[mt][2], alf[mt][3], addr);
            }
            uint32_t bhf[4][4], blf[4][4];
#pragma unroll
            for (int np = 0; np < 4; np++) {
                uint32_t addr = Bh + (b_row + np * 16) * ROWB + (k0 + b_k8) * 2;
                LDSM_X4(bhf[np][0], bhf[np][1], bhf[np][2], bhf[np][3], addr);
                addr = Bl + (b_row + np * 16) * ROWB + (k0 + b_k8) * 2;
                LDSM_X4(blf[np][0], blf[np][1], blf[np][2], blf[np][3], addr);
            }
#pragma unroll
            for (int mt = 0; mt < 2; mt++) {
#pragma unroll
                for (int np = 0; np < 4; np++) {
                    MMA_BF16(acc[mt][2 * np],     ahf[mt], bhf[np][0], bhf[np][1]);
                    MMA_BF16(acc[mt][2 * np + 1], ahf[mt], bhf[np][2], bhf[np][3]);
                    MMA_BF16(acc[mt][2 * np],     ahf[mt], blf[np][0], blf[np][1]);
                    MMA_BF16(acc[mt][2 * np + 1], ahf[mt], blf[np][2], blf[np][3]);
                    MMA_BF16(acc[mt][2 * np],     alf[mt], bhf[np][0], bhf[np][1]);
                    MMA_BF16(acc[mt][2 * np + 1], alf[mt], bhf[np][2], bhf[np][3]);
                }
            }
        }

        if (c + 1 < NCH) {
            __syncthreads();   // all warps done reading smem of chunk c
            *(uint4*)(smem + 0 * TILE_B + soff)      = ah2[0];
            *(uint4*)(smem + 0 * TILE_B + soff + 16) = ah2[1];
            *(uint4*)(smem + 1 * TILE_B + soff)      = al2[0];
            *(uint4*)(smem + 1 * TILE_B + soff + 16) = al2[1];
            *(uint4*)(smem + 2 * TILE_B + soff)      = bh2[0];
            *(uint4*)(smem + 2 * TILE_B + soff + 16) = bh2[1];
            *(uint4*)(smem + 3 * TILE_B + soff)      = bl2[0];
            *(uint4*)(smem + 3 * TILE_B + soff + 16) = bl2[1];
            __syncthreads();   // stores visible before next chunk's ldmatrix
        }
    }

    // epilogue
    const int mw = m0 + wm * 32;
    const int nw = wn * 64;
#pragma unroll
    for (int mt = 0; mt < 2; mt++) {
#pragma unroll
        for (int nt = 0; nt < 8; nt++) {
            int mr = mw + mt * 16 + (lane >> 2);
            int nc = nw + nt * 8 + (lane & 3) * 2;
            if (mr < NN)
                *(float2*)(g_acc + (size_t)mr * CC + nc) =
                    make_float2(acc[mt][nt][0], acc[mt][nt][1]);
            if (mr + 8 < NN)
                *(float2*)(g_acc + (size_t)(mr + 8) * CC + nc) =
                    make_float2(acc[mt][nt][2], acc[mt][nt][3]);
        }
    }
}

// ---------------- BN ----------------
__global__ void k_zero_bn() {
    if (threadIdx.x < CC) { g_bnsum[threadIdx.x] = 0.f; g_bnsq[threadIdx.x] = 0.f; }
}

__global__ void k_bnstat() {
    int c = threadIdx.x;
    float s = 0.f, q = 0.f;
    for (int r = blockIdx.x; r < NN; r += gridDim.x) {
        float v = g_acc[(size_t)r * CC + c];
        s += v; q += v * v;
    }
    atomicAdd(&g_bnsum[c], s);
    atomicAdd(&g_bnsq[c], q);
}

__global__ void k_bnfinal(const float* __restrict__ gA, const float* __restrict__ bA,
                          const float* __restrict__ gB, const float* __restrict__ bB) {
    int c = threadIdx.x;
    if (c >= CC) return;
    float mu = g_bnsum[c] * (1.0f / NN);
    float var = g_bnsq[c] * (1.0f / NN) - mu * mu;
    float gv, bv;
    if (gB != nullptr && c >= OUTC) { gv = gB[c - OUTC]; bv = bB[c - OUTC]; }
    else                            { gv = gA[c];        bv = bA[c]; }
    float sc = rsqrtf(var + EPSF) * gv;
    g_scale[c] = sc;
    g_shift[c] = bv - mu * sc;
}

__global__ void k_bnrelu() {
    size_t i = (size_t)blockIdx.x * blockDim.x + threadIdx.x;
    if (i < (size_t)NN * CC) {
        int c = (int)(i & 127);
        float v = g_acc[i] * g_scale[c] + g_shift[c];
        g_h[i] = fmaxf(v, 0.f);
    }
}

__global__ void k_out(float* __restrict__ out) {
    size_t i = (size_t)blockIdx.x * blockDim.x + threadIdx.x;
    if (i < (size_t)NN * CC) {
        int c = (int)(i & 127);
        size_t r = i >> 7;
        float v = g_acc[i] * g_scale[c] + g_shift[c];
        if (c < OUTC) out[r * OUTC + c] = v;
        else          out[(size_t)NN * OUTC + r * OUTC + (c - OUTC)] = v;
    }
}

// ---------------- launcher ----------------
extern "C" void kernel_launch(void* const* d_in, const int* in_sizes, int n_in,
                              void* d_out, int out_size) {
    const float* x   = (const float*)d_in[0];
    const int*   ei  = (const int*)d_in[1];
    const float* W1  = (const float*)d_in[2];
    const float* g1  = (const float*)d_in[4];
    const float* be1 = (const float*)d_in[5];
    const float* W2  = (const float*)d_in[6];
    const float* g2  = (const float*)d_in[8];
    const float* be2 = (const float*)d_in[9];
    const float* W3  = (const float*)d_in[10];
    const float* g3  = (const float*)d_in[12];
    const float* be3 = (const float*)d_in[13];
    const int* src = ei;
    const int* dst = ei + EE;
    float* out = (float*)d_out;

    const int NB_N = (NN + 255) / 256;
    const int NB_E = (EE + 255) / 256;
    const int NB_PROP = (NN * 32 + 255) / 256;
    const int NB_ELT = (NN * CC + 255) / 256;
    const int NB_MM = (NN + 127) / 128;   // 391

    // graph preprocessing (CSR by dst + edge weights)
    k_zero_prep<<<NB_N, 256>>>();
    k_count<<<NB_E, 256>>>(src, dst);
    k_dinv<<<NB_N, 256>>>();
    k_scan1<<<NBLK, 512>>>();
    k_scan2<<<1, 128>>>();
    k_scan3<<<NB_N, 256>>>();
    k_fill<<<NB_E, 256>>>(src, dst);

    // weight packing (transpose + bf16 hi/lo split)
    k_packW1<<<(KK1 * CC * CC + 255) / 256, 256>>>(W1);
    k_packW23<<<(KK2 * CC * CC + 255) / 256, 256>>>(W2, W3);

    // ---- layer 1: Chebyshev K=16 on x ----
    k_copyT0<<<NB_PROP, 256>>>(x, 0);
    k_prop<<<NB_PROP, 256>>>(-1, -1, 1, 1.0f, x);
    for (int k = 2; k < KK1; k++)
        k_prop<<<NB_PROP, 256>>>(k - 1, k - 2, k, 2.0f, nullptr);
    k_mm<<<NB_MM, 256>>>(0);
    k_zero_bn<<<1, 128>>>();
    k_bnstat<<<256, 128>>>();
    k_bnfinal<<<1, 128>>>(g1, be1, nullptr, nullptr);
    k_bnrelu<<<NB_ELT, 256>>>();

    // ---- layers 2+3 share propagations of h ----
    k_copyT0<<<NB_PROP, 256>>>(nullptr, 1);
    k_prop<<<NB_PROP, 256>>>(0, -1, 1, 1.0f, nullptr);
    for (int k = 2; k < KK2; k++)
        k_prop<<<NB_PROP, 256>>>(k - 1, k - 2, k, 2.0f, nullptr);
    k_mm<<<NB_MM, 256>>>(1);
    k_zero_bn<<<1, 128>>>();
    k_bnstat<<<256, 128>>>();
    k_bnfinal<<<1, 128>>>(g2, be2, g3, be3);
    k_out<<<NB_ELT, 256>>>(out);
}

// round 7
// speedup vs baseline: 1.2793x; 1.0249x over previous
#include <cuda_runtime.h>
#include <cuda_bf16.h>
#include <cstdint>

#define NN   50000
#define EE   800000
#define CC   128
#define OUTC 64
#define KK1  16
#define KK2  8
#define EPSF 1e-5f
#define NBLK 98      // ceil(NN/512)

// ---------------- scratch (device globals; no allocation) ----------------
__device__ float g_dinv[NN];
__device__ int   g_outdeg[NN];
__device__ int   g_indeg[NN];
__device__ int   g_rowptr[NN + 1];
__device__ int   g_fill[NN];
__device__ int2  g_cw[EE];                          // packed (col, w bits)
__device__ float g_T[(size_t)KK1 * NN * CC];        // fp32 Chebyshev blocks; block 0 = h in phase 2
__device__ float g_acc[(size_t)NN * CC];            // GEMM output / pre-BN
__device__ __nv_bfloat16 g_Whi1[CC * (KK1 * CC)];   // [n=128][k=2048]
__device__ __nv_bfloat16 g_Wlo1[CC * (KK1 * CC)];
__device__ __nv_bfloat16 g_Whi23[CC * (KK2 * CC)];  // [n=128][k=1024], packed [W2|W3]
__device__ __nv_bfloat16 g_Wlo23[CC * (KK2 * CC)];
__device__ float g_bnsum[CC];
__device__ float g_bnsq[CC];
__device__ float g_scale[CC];
__device__ float g_shift[CC];
__device__ int   g_bsums[NBLK];

// ---------------- PTX helpers (sm_80+ baseline features only) ----------------
__device__ __forceinline__ uint32_t smem_u32(const void* p) {
    uint32_t a;
    asm("{ .reg .u64 t; cvta.to.shared.u64 t, %1; cvt.u32.u64 %0, t; }" : "=r"(a) : "l"(p));
    return a;
}

#define LDSM_X4(r0, r1, r2, r3, addr)                                     \
    asm volatile("ldmatrix.sync.aligned.m8n8.x4.shared.b16 {%0,%1,%2,%3}, [%4];" \
        : "=r"(r0), "=r"(r1), "=r"(r2), "=r"(r3) : "r"(addr))

#define MMA_BF16(d, a, b0, b1)                                            \
    asm volatile("mma.sync.aligned.m16n8k16.row.col.f32.bf16.bf16.f32 "   \
        "{%0,%1,%2,%3}, {%4,%5,%6,%7}, {%8,%9}, {%0,%1,%2,%3};"           \
        : "+f"((d)[0]), "+f"((d)[1]), "+f"((d)[2]), "+f"((d)[3])          \
        : "r"((a)[0]), "r"((a)[1]), "r"((a)[2]), "r"((a)[3]),             \
          "r"(b0), "r"(b1))

// ---------------- setup kernels ----------------
__global__ void k_zero_prep() {
    int i = blockIdx.x * blockDim.x + threadIdx.x;
    if (i < NN) { g_outdeg[i] = 0; g_indeg[i] = 0; g_fill[i] = 0; }
}

__global__ void k_count(const int* __restrict__ src, const int* __restrict__ dst) {
    int e = blockIdx.x * blockDim.x + threadIdx.x;
    if (e < EE) {
        atomicAdd(&g_outdeg[src[e]], 1);
        atomicAdd(&g_indeg[dst[e]], 1);
    }
}

__global__ void k_dinv() {
    int i = blockIdx.x * blockDim.x + threadIdx.x;
    if (i < NN) {
        int d = g_outdeg[i];
        g_dinv[i] = (d > 0) ? rsqrtf((float)d) : 0.0f;
    }
}

__global__ void k_scan1() {
    __shared__ int s[512];
    int t = threadIdx.x;
    int i = blockIdx.x * 512 + t;
    int v = (i < NN) ? g_indeg[i] : 0;
    s[t] = v;
    __syncthreads();
    for (int off = 1; off < 512; off <<= 1) {
        int a = (t >= off) ? s[t - off] : 0;
        __syncthreads();
        s[t] += a;
        __syncthreads();
    }
    if (i < NN) g_rowptr[i] = s[t] - v;
    if (t == 511) g_bsums[blockIdx.x] = s[511];
}

__global__ void k_scan2() {
    __shared__ int s[128];
    int t = threadIdx.x;
    int v = (t < NBLK) ? g_bsums[t] : 0;
    s[t] = v;
    __syncthreads();
    for (int off = 1; off < 128; off <<= 1) {
        int a = (t >= off) ? s[t - off] : 0;
        __syncthreads();
        s[t] += a;
        __syncthreads();
    }
    if (t < NBLK) g_bsums[t] = s[t] - v;
}

__global__ void k_scan3() {
    int i = blockIdx.x * blockDim.x + threadIdx.x;
    if (i < NN) g_rowptr[i] += g_bsums[i >> 9];
    if (i == 0) g_rowptr[NN] = EE;
}

__global__ void k_fill(const int* __restrict__ src, const int* __restrict__ dst) {
    int e = blockIdx.x * blockDim.x + threadIdx.x;
    if (e < EE) {
        int s = src[e], d = dst[e];
        int p = g_rowptr[d] + atomicAdd(&g_fill[d], 1);
        float w = -g_dinv[s] * g_dinv[d];
        g_cw[p] = make_int2(s, __float_as_int(w));
    }
}

// ---------------- propagation (dst-CSR SpMM), one warp per node ----------------
// z source: zk<0 -> xext, else g_T block zk.  subtract: subk==-1 none,
// subk==-2 -> xext, else g_T block subk.
__global__ void k_prop(int zk, int subk, int outk, float alpha,
                       const float* __restrict__ xext) {
    int gw = (blockIdx.x * blockDim.x + threadIdx.x) >> 5;
    int lane = threadIdx.x & 31;
    if (gw >= NN) return;
    const float* z = (zk < 0) ? xext : (g_T + (size_t)zk * NN * CC);
    int beg = g_rowptr[gw], end = g_rowptr[gw + 1];
    float4 acc = make_float4(0.f, 0.f, 0.f, 0.f);
    int co = lane << 2;
    int e = beg;
    for (; e + 2 <= end; e += 2) {
        int2 cw0 = __ldg(&g_cw[e]);
        int2 cw1 = __ldg(&g_cw[e + 1]);
        float4 v0 = *(const float4*)(z + (size_t)cw0.x * CC + co);
        float4 v1 = *(const float4*)(z + (size_t)cw1.x * CC + co);
        float w0 = __int_as_float(cw0.y);
        float w1 = __int_as_float(cw1.y);
        acc.x += w0 * v0.x; acc.y += w0 * v0.y;
        acc.z += w0 * v0.z; acc.w += w0 * v0.w;
        acc.x += w1 * v1.x; acc.y += w1 * v1.y;
        acc.z += w1 * v1.z; acc.w += w1 * v1.w;
    }
    if (e < end) {
        int2 cw = __ldg(&g_cw[e]);
        float4 v = *(const float4*)(z + (size_t)cw.x * CC + co);
        float w = __int_as_float(cw.y);
        acc.x += w * v.x; acc.y += w * v.y;
        acc.z += w * v.z; acc.w += w * v.w;
    }
    size_t o = (size_t)gw * CC + co;
    float4 r;
    if (subk != -1) {
        const float* sp = (subk == -2) ? xext : (g_T + (size_t)subk * NN * CC);
        float4 s = *(const float4*)(sp + o);
        r = make_float4(alpha * acc.x - s.x, alpha * acc.y - s.y,
                        alpha * acc.z - s.z, alpha * acc.w - s.w);
    } else {
        r = make_float4(alpha * acc.x, alpha * acc.y, alpha * acc.z, alpha * acc.w);
    }
    *(float4*)(g_T + (size_t)outk * NN * CC + o) = r;
}

// ---------------- weight pack: fp32 [K][N] -> bf16 hi/lo [N][K] ----------------
__global__ void k_packW1(const float* __restrict__ W1) {
    int i = blockIdx.x * blockDim.x + threadIdx.x;
    if (i < KK1 * CC * CC) {
        int kk = i >> 7, n = i & 127;
        float v = W1[i];
        __nv_bfloat16 h = __float2bfloat16(v);
        g_Whi1[(size_t)n * (KK1 * CC) + kk] = h;
        g_Wlo1[(size_t)n * (KK1 * CC) + kk] = __float2bfloat16(v - __bfloat162float(h));
    }
}

__global__ void k_packW23(const float* __restrict__ W2, const float* __restrict__ W3) {
    int i = blockIdx.x * blockDim.x + threadIdx.x;
    if (i < KK2 * CC * CC) {
        int kk = i >> 7, n = i & 127;
        float v = (n < OUTC) ? W2[(size_t)kk * OUTC + n]
                             : W3[(size_t)kk * OUTC + (n - OUTC)];
        __nv_bfloat16 h = __float2bfloat16(v);
        g_Whi23[(size_t)n * (KK2 * CC) + kk] = h;
        g_Wlo23[(size_t)n * (KK2 * CC) + kk] = __float2bfloat16(v - __bfloat162float(h));
    }
}

// ---------------- mma.sync GEMM: g_acc[NN x 128] = T @ W (3-term bf16 split) ----------------
// BM=128, BN=128, BK=32. 256 threads = 8 warps (4m x 2n), warp tile 32x64.
// A block 0 comes from A0 (external x) when non-null, else g_T block 0.
#define ROWB   80                  // smem row stride bytes (32 bf16 + 16B pad)
#define TILE_B (128 * ROWB)        // 10240 per tile

__device__ __forceinline__ uint32_t pack2(float a, float b) {
    __nv_bfloat162 t = __floats2bfloat162_rn(a, b);
    return *reinterpret_cast<uint32_t*>(&t);
}
__device__ __forceinline__ float resid(float v) {
    return v - __bfloat162float(__float2bfloat16(v));
}

__global__ __launch_bounds__(256) void k_mm(int which, const float* __restrict__ A0) {
    __shared__ __align__(16) char smem[4 * TILE_B];   // Ah | Al | Bh | Bl
    const __nv_bfloat16* __restrict__ Bhi = which ? g_Whi23 : g_Whi1;
    const __nv_bfloat16* __restrict__ Blo = which ? g_Wlo23 : g_Wlo1;
    const int Ktot = which ? (KK2 * CC) : (KK1 * CC);

    const uint32_t sm = smem_u32(smem);
    const uint32_t Ah = sm, Al = sm + TILE_B, Bh = sm + 2 * TILE_B, Bl = sm + 3 * TILE_B;
    const int tid = threadIdx.x;
    const int lane = tid & 31;
    const int w = tid >> 5;
    const int wm = w & 3;                 // m-warp 0..3 (32 rows each)
    const int wn = w >> 2;                // n-warp 0..1 (64 cols each)
    const int m0 = blockIdx.x * 128;
    const int NCH = Ktot >> 5;

    // copy mapping: row cr = tid>>1 (0..127), half cs = tid&1 (16 elems)
    const int cr = tid >> 1;
    const int cs = tid & 1;
    const int arow = m0 + cr;

    uint4 ah2[2], al2[2], bh2[2], bl2[2];

    auto load_regs = [&](int c) {
        int blk = c >> 2;
        const float* abase = (blk == 0 && A0 != nullptr)
                             ? A0 : (g_T + (size_t)blk * NN * CC);
        float4 fa[4];
        if (arow < NN) {
            const float4* pa = (const float4*)(abase + (size_t)arow * CC + (c & 3) * 32 + cs * 16);
#pragma unroll
            for (int i = 0; i < 4; i++) fa[i] = pa[i];
        } else {
#pragma unroll
            for (int i = 0; i < 4; i++) fa[i] = make_float4(0.f, 0.f, 0.f, 0.f);
        }
#pragma unroll
        for (int i = 0; i < 2; i++) {
            float4 f0 = fa[2 * i], f1 = fa[2 * i + 1];
            ah2[i] = make_uint4(pack2(f0.x, f0.y), pack2(f0.z, f0.w),
                                pack2(f1.x, f1.y), pack2(f1.z, f1.w));
            al2[i] = make_uint4(pack2(resid(f0.x), resid(f0.y)),
                                pack2(resid(f0.z), resid(f0.w)),
                                pack2(resid(f1.x), resid(f1.y)),
                                pack2(resid(f1.z), resid(f1.w)));
        }
        size_t gb = (size_t)cr * Ktot + c * 32 + cs * 16;
        const uint4* pw = (const uint4*)(Bhi + gb);
        const uint4* pl = (const uint4*)(Blo + gb);
        bh2[0] = pw[0]; bh2[1] = pw[1];
        bl2[0] = pl[0]; bl2[1] = pl[1];
    };

    float acc[2][8][4];
#pragma unroll
    for (int i = 0; i < 2; i++)
#pragma unroll
        for (int j = 0; j < 8; j++)
#pragma unroll
            for (int q = 0; q < 4; q++) acc[i][j][q] = 0.f;

    const uint32_t a_row = wm * 32 + (lane & 15);
    const uint32_t a_k8  = (lane >> 4) << 3;
    const uint32_t b_row = wn * 64 + ((lane >> 4) << 3) + (lane & 7);
    const uint32_t b_k8  = ((lane >> 3) & 1) << 3;
    const uint32_t soff = (uint32_t)(cr * ROWB + cs * 32);

    load_regs(0);
    {
        *(uint4*)(smem + 0 * TILE_B + soff)      = ah2[0];
        *(uint4*)(smem + 0 * TILE_B + soff + 16) = ah2[1];
        *(uint4*)(smem + 1 * TILE_B + soff)      = al2[0];
        *(uint4*)(smem + 1 * TILE_B + soff + 16) = al2[1];
        *(uint4*)(smem + 2 * TILE_B + soff)      = bh2[0];
        *(uint4*)(smem + 2 * TILE_B + soff + 16) = bh2[1];
        *(uint4*)(smem + 3 * TILE_B + soff)      = bl2[0];
        *(uint4*)(smem + 3 * TILE_B + soff + 16) = bl2[1];
    }
    __syncthreads();

    for (int c = 0; c < NCH; c++) {
        if (c + 1 < NCH) load_regs(c + 1);

#pragma unroll
        for (int ks = 0; ks < 2; ks++) {
            const uint32_t k0 = ks * 16;
            uint32_t ahf[2][4], alf[2][4];
#pragma unroll
            for (int mt = 0; mt < 2; mt++) {
                uint32_t addr = Ah + (a_row + mt * 16) * ROWB + (k0 + a_k8) * 2;
                LDSM_X4(ahf[mt][0], ahf[mt][1], ahf[mt][2], ahf[mt][3], addr);
                addr = Al + (a_row + mt * 16) * ROWB + (k0 + a_k8) * 2;
                LDSM_X4(alf[mt][0], alf[mt][1], alf[mt][2], alf[mt][3], addr);
            }
            uint32_t bhf[4][4], blf[4][4];
#pragma unroll
            for (int np = 0; np < 4; np++) {
                uint32_t addr = Bh + (b_row + np * 16) * ROWB + (k0 + b_k8) * 2;
                LDSM_X4(bhf[np][0], bhf[np][1], bhf[np][2], bhf[np][3], addr);
                addr = Bl + (b_row + np * 16) * ROWB + (k0 + b_k8) * 2;
                LDSM_X4(blf[np][0], blf[np][1], blf[np][2], blf[np][3], addr);
            }
#pragma unroll
            for (int mt = 0; mt < 2; mt++) {
#pragma unroll
                for (int np = 0; np < 4; np++) {
                    MMA_BF16(acc[mt][2 * np],     ahf[mt], bhf[np][0], bhf[np][1]);
                    MMA_BF16(acc[mt][2 * np + 1], ahf[mt], bhf[np][2], bhf[np][3]);
                    MMA_BF16(acc[mt][2 * np],     ahf[mt], blf[np][0], blf[np][1]);
                    MMA_BF16(acc[mt][2 * np + 1], ahf[mt], blf[np][2], blf[np][3]);
                    MMA_BF16(acc[mt][2 * np],     alf[mt], bhf[np][0], bhf[np][1]);
                    MMA_BF16(acc[mt][2 * np + 1], alf[mt], bhf[np][2], bhf[np][3]);
                }
            }
        }

        if (c + 1 < NCH) {
            __syncthreads();
            *(uint4*)(smem + 0 * TILE_B + soff)      = ah2[0];
            *(uint4*)(smem + 0 * TILE_B + soff + 16) = ah2[1];
            *(uint4*)(smem + 1 * TILE_B + soff)      = al2[0];
            *(uint4*)(smem + 1 * TILE_B + soff + 16) = al2[1];
            *(uint4*)(smem + 2 * TILE_B + soff)      = bh2[0];
            *(uint4*)(smem + 2 * TILE_B + soff + 16) = bh2[1];
            *(uint4*)(smem + 3 * TILE_B + soff)      = bl2[0];
            *(uint4*)(smem + 3 * TILE_B + soff + 16) = bl2[1];
            __syncthreads();
        }
    }

    const int mw = m0 + wm * 32;
    const int nw = wn * 64;
#pragma unroll
    for (int mt = 0; mt < 2; mt++) {
#pragma unroll
        for (int nt = 0; nt < 8; nt++) {
            int mr = mw + mt * 16 + (lane >> 2);
            int nc = nw + nt * 8 + (lane & 3) * 2;
            if (mr < NN)
                *(float2*)(g_acc + (size_t)mr * CC + nc) =
                    make_float2(acc[mt][nt][0], acc[mt][nt][1]);
            if (mr + 8 < NN)
                *(float2*)(g_acc + (size_t)(mr + 8) * CC + nc) =
                    make_float2(acc[mt][nt][2], acc[mt][nt][3]);
        }
    }
}

// ---------------- BN ----------------
__global__ void k_zero_bn() {
    if (threadIdx.x < CC) { g_bnsum[threadIdx.x] = 0.f; g_bnsq[threadIdx.x] = 0.f; }
}

__global__ void k_bnstat() {
    int c = threadIdx.x;
    float s = 0.f, q = 0.f;
    for (int r = blockIdx.x; r < NN; r += gridDim.x) {
        float v = g_acc[(size_t)r * CC + c];
        s += v; q += v * v;
    }
    atomicAdd(&g_bnsum[c], s);
    atomicAdd(&g_bnsq[c], q);
}

__global__ void k_bnfinal(const float* __restrict__ gA, const float* __restrict__ bA,
                          const float* __restrict__ gB, const float* __restrict__ bB) {
    int c = threadIdx.x;
    if (c >= CC) return;
    float mu = g_bnsum[c] * (1.0f / NN);
    float var = g_bnsq[c] * (1.0f / NN) - mu * mu;
    float gv, bv;
    if (gB != nullptr && c >= OUTC) { gv = gB[c - OUTC]; bv = bB[c - OUTC]; }
    else                            { gv = gA[c];        bv = bA[c]; }
    float sc = rsqrtf(var + EPSF) * gv;
    g_scale[c] = sc;
    g_shift[c] = bv - mu * sc;
}

// BN+ReLU, writing h straight into g_T block 0 (layer-2's T0)
__global__ void k_bnrelu() {
    size_t i = (size_t)blockIdx.x * blockDim.x + threadIdx.x;
    if (i < (size_t)NN * CC) {
        int c = (int)(i & 127);
        float v = g_acc[i] * g_scale[c] + g_shift[c];
        g_T[i] = fmaxf(v, 0.f);
    }
}

__global__ void k_out(float* __restrict__ out) {
    size_t i = (size_t)blockIdx.x * blockDim.x + threadIdx.x;
    if (i < (size_t)NN * CC) {
        int c = (int)(i & 127);
        size_t r = i >> 7;
        float v = g_acc[i] * g_scale[c] + g_shift[c];
        if (c < OUTC) out[r * OUTC + c] = v;
        else          out[(size_t)NN * OUTC + r * OUTC + (c - OUTC)] = v;
    }
}

// ---------------- launcher ----------------
extern "C" void kernel_launch(void* const* d_in, const int* in_sizes, int n_in,
                              void* d_out, int out_size) {
    const float* x   = (const float*)d_in[0];
    const int*   ei  = (const int*)d_in[1];
    const float* W1  = (const float*)d_in[2];
    const float* g1  = (const float*)d_in[4];
    const float* be1 = (const float*)d_in[5];
    const float* W2  = (const float*)d_in[6];
    const float* g2  = (const float*)d_in[8];
    const float* be2 = (const float*)d_in[9];
    const float* W3  = (const float*)d_in[10];
    const float* g3  = (const float*)d_in[12];
    const float* be3 = (const float*)d_in[13];
    const int* src = ei;
    const int* dst = ei + EE;
    float* out = (float*)d_out;

    const int NB_N = (NN + 255) / 256;
    const int NB_E = (EE + 255) / 256;
    const int NB_PROP = (NN * 32 + 127) / 128;       // 128-thread blocks
    const int NB_ELT = (NN * CC + 255) / 256;
    const int NB_MM = (NN + 127) / 128;              // 391

    // graph preprocessing (CSR by dst + packed edge weights)
    k_zero_prep<<<NB_N, 256>>>();
    k_count<<<NB_E, 256>>>(src, dst);
    k_dinv<<<NB_N, 256>>>();
    k_scan1<<<NBLK, 512>>>();
    k_scan2<<<1, 128>>>();
    k_scan3<<<NB_N, 256>>>();
    k_fill<<<NB_E, 256>>>(src, dst);

    // weight packing (transpose + bf16 hi/lo split)
    k_packW1<<<(KK1 * CC * CC + 255) / 256, 256>>>(W1);
    k_packW23<<<(KK2 * CC * CC + 255) / 256, 256>>>(W2, W3);

    // ---- layer 1: Chebyshev K=16 on x (T0 = x read in place) ----
    k_prop<<<NB_PROP, 128>>>(-1, -1, 1, 1.0f, x);        // T1 = P x
    k_prop<<<NB_PROP, 128>>>(1, -2, 2, 2.0f, x);         // T2 = 2 P T1 - x
    for (int k = 3; k < KK1; k++)
        k_prop<<<NB_PROP, 128>>>(k - 1, k - 2, k, 2.0f, x);
    k_mm<<<NB_MM, 256>>>(0, x);                          // block 0 <- x
    k_zero_bn<<<1, 128>>>();
    k_bnstat<<<256, 128>>>();
    k_bnfinal<<<1, 128>>>(g1, be1, nullptr, nullptr);
    k_bnrelu<<<NB_ELT, 256>>>();                         // h -> g_T block 0

    // ---- layers 2+3 share propagations of h (= g_T block 0) ----
    k_prop<<<NB_PROP, 128>>>(0, -1, 1, 1.0f, nullptr);   // T1 = P h
    k_prop<<<NB_PROP, 128>>>(1, 0, 2, 2.0f, nullptr);    // T2 = 2 P T1 - h
    for (int k = 3; k < KK2; k++)
        k_prop<<<NB_PROP, 128>>>(k - 1, k - 2, k, 2.0f, nullptr);
    k_mm<<<NB_MM, 256>>>(1, nullptr);
    k_zero_bn<<<1, 128>>>();
    k_bnstat<<<256, 128>>>();
    k_bnfinal<<<1, 128>>>(g2, be2, g3, be3);
    k_out<<<NB_ELT, 256>>>(out);
}

// round 10
// speedup vs baseline: 1.2872x; 1.0062x over previous
#include <cuda_runtime.h>
#include <cuda_bf16.h>
#include <cstdint>

#define NN   50000
#define EE   800000
#define CC   128
#define OUTC 64
#define KK1  16
#define KK2  8
#define EPSF 1e-5f
#define NBLK 98      // ceil(NN/512)

// ---------------- scratch (device globals; no allocation) ----------------
__device__ float g_dinv[NN];
__device__ int   g_outdeg[NN];
__device__ int   g_indeg[NN];
__device__ int   g_rowptr[NN + 1];
__device__ int   g_fill[NN];
__device__ int2  g_cw[EE];                          // packed (col, w bits)
__device__ float g_T[(size_t)KK1 * NN * CC];        // fp32 Chebyshev blocks; block 0 = h in phase 2
__device__ float g_acc[(size_t)NN * CC];            // GEMM output / pre-BN
__device__ __nv_bfloat16 g_Whi1[CC * (KK1 * CC)];   // [n=128][k=2048]
__device__ __nv_bfloat16 g_Wlo1[CC * (KK1 * CC)];
__device__ __nv_bfloat16 g_Whi23[CC * (KK2 * CC)];  // [n=128][k=1024], packed [W2|W3]
__device__ __nv_bfloat16 g_Wlo23[CC * (KK2 * CC)];
__device__ float g_bnsum[CC];
__device__ float g_bnsq[CC];
__device__ float g_scale[CC];
__device__ float g_shift[CC];
__device__ int   g_bsums[NBLK];

// ---------------- PTX helpers (sm_80+ baseline features only) ----------------
__device__ __forceinline__ uint32_t smem_u32(const void* p) {
    uint32_t a;
    asm("{ .reg .u64 t; cvta.to.shared.u64 t, %1; cvt.u32.u64 %0, t; }" : "=r"(a) : "l"(p));
    return a;
}

#define LDSM_X4(r0, r1, r2, r3, addr)                                     \
    asm volatile("ldmatrix.sync.aligned.m8n8.x4.shared.b16 {%0,%1,%2,%3}, [%4];" \
        : "=r"(r0), "=r"(r1), "=r"(r2), "=r"(r3) : "r"(addr))

#define MMA_BF16(d, a, b0, b1)                                            \
    asm volatile("mma.sync.aligned.m16n8k16.row.col.f32.bf16.bf16.f32 "   \
        "{%0,%1,%2,%3}, {%4,%5,%6,%7}, {%8,%9}, {%0,%1,%2,%3};"           \
        : "+f"((d)[0]), "+f"((d)[1]), "+f"((d)[2]), "+f"((d)[3])          \
        : "r"((a)[0]), "r"((a)[1]), "r"((a)[2]), "r"((a)[3]),             \
          "r"(b0), "r"(b1))

// ---------------- setup kernels ----------------
__global__ void k_zero_prep() {
    int i = blockIdx.x * blockDim.x + threadIdx.x;
    if (i < NN) { g_outdeg[i] = 0; g_indeg[i] = 0; g_fill[i] = 0; }
}

__global__ void k_count(const int* __restrict__ src, const int* __restrict__ dst) {
    int e = blockIdx.x * blockDim.x + threadIdx.x;
    if (e < EE) {
        atomicAdd(&g_outdeg[src[e]], 1);
        atomicAdd(&g_indeg[dst[e]], 1);
    }
}

// scan phase 1 + dinv (both depend only on k_count)
__global__ void k_scan1() {
    __shared__ int s[512];
    int t = threadIdx.x;
    int i = blockIdx.x * 512 + t;
    if (i < NN) {
        int d = g_outdeg[i];
        g_dinv[i] = (d > 0) ? rsqrtf((float)d) : 0.0f;
    }
    int v = (i < NN) ? g_indeg[i] : 0;
    s[t] = v;
    __syncthreads();
    for (int off = 1; off < 512; off <<= 1) {
        int a = (t >= off) ? s[t - off] : 0;
        __syncthreads();
        s[t] += a;
        __syncthreads();
    }
    if (i < NN) g_rowptr[i] = s[t] - v;
    if (t == 511) g_bsums[blockIdx.x] = s[511];
}

__global__ void k_scan2() {
    __shared__ int s[128];
    int t = threadIdx.x;
    int v = (t < NBLK) ? g_bsums[t] : 0;
    s[t] = v;
    __syncthreads();
    for (int off = 1; off < 128; off <<= 1) {
        int a = (t >= off) ? s[t - off] : 0;
        __syncthreads();
        s[t] += a;
        __syncthreads();
    }
    if (t < NBLK) g_bsums[t] = s[t] - v;
}

__global__ void k_scan3() {
    int i = blockIdx.x * blockDim.x + threadIdx.x;
    if (i < NN) g_rowptr[i] += g_bsums[i >> 9];
    if (i == 0) g_rowptr[NN] = EE;
}

__global__ void k_fill(const int* __restrict__ src, const int* __restrict__ dst) {
    int e = blockIdx.x * blockDim.x + threadIdx.x;
    if (e < EE) {
        int s = src[e], d = dst[e];
        int p = g_rowptr[d] + atomicAdd(&g_fill[d], 1);
        float w = -g_dinv[s] * g_dinv[d];
        g_cw[p] = make_int2(s, __float_as_int(w));
    }
}

// ---------------- propagation (dst-CSR SpMM), one warp per node ----------------
__global__ void k_prop(int zk, int subk, int outk, float alpha,
                       const float* __restrict__ xext) {
    int gw = (blockIdx.x * blockDim.x + threadIdx.x) >> 5;
    int lane = threadIdx.x & 31;
    if (gw >= NN) return;
    const float* z = (zk < 0) ? xext : (g_T + (size_t)zk * NN * CC);
    int beg = g_rowptr[gw], end = g_rowptr[gw + 1];
    float4 acc = make_float4(0.f, 0.f, 0.f, 0.f);
    int co = lane << 2;
    int e = beg;
    for (; e + 4 <= end; e += 4) {
        int2 cw0 = __ldg(&g_cw[e]);
        int2 cw1 = __ldg(&g_cw[e + 1]);
        int2 cw2 = __ldg(&g_cw[e + 2]);
        int2 cw3 = __ldg(&g_cw[e + 3]);
        float4 v0 = *(const float4*)(z + (size_t)cw0.x * CC + co);
        float4 v1 = *(const float4*)(z + (size_t)cw1.x * CC + co);
        float4 v2 = *(const float4*)(z + (size_t)cw2.x * CC + co);
        float4 v3 = *(const float4*)(z + (size_t)cw3.x * CC + co);
        float w0 = __int_as_float(cw0.y);
        float w1 = __int_as_float(cw1.y);
        float w2 = __int_as_float(cw2.y);
        float w3 = __int_as_float(cw3.y);
        acc.x += w0 * v0.x; acc.y += w0 * v0.y; acc.z += w0 * v0.z; acc.w += w0 * v0.w;
        acc.x += w1 * v1.x; acc.y += w1 * v1.y; acc.z += w1 * v1.z; acc.w += w1 * v1.w;
        acc.x += w2 * v2.x; acc.y += w2 * v2.y; acc.z += w2 * v2.z; acc.w += w2 * v2.w;
        acc.x += w3 * v3.x; acc.y += w3 * v3.y; acc.z += w3 * v3.z; acc.w += w3 * v3.w;
    }
    for (; e < end; e++) {
        int2 cw = __ldg(&g_cw[e]);
        float4 v = *(const float4*)(z + (size_t)cw.x * CC + co);
        float w = __int_as_float(cw.y);
        acc.x += w * v.x; acc.y += w * v.y;
        acc.z += w * v.z; acc.w += w * v.w;
    }
    size_t o = (size_t)gw * CC + co;
    float4 r;
    if (subk != -1) {
        const float* sp = (subk == -2) ? xext : (g_T + (size_t)subk * NN * CC);
        float4 s = *(const float4*)(sp + o);
        r = make_float4(alpha * acc.x - s.x, alpha * acc.y - s.y,
                        alpha * acc.z - s.z, alpha * acc.w - s.w);
    } else {
        r = make_float4(alpha * acc.x, alpha * acc.y, alpha * acc.z, alpha * acc.w);
    }
    *(float4*)(g_T + (size_t)outk * NN * CC + o) = r;
}

// ---------------- weight pack (fused): fp32 [K][N] -> bf16 hi/lo [N][K] ----------------
__global__ void k_packW(const float* __restrict__ W1, const float* __restrict__ W2,
                        const float* __restrict__ W3) {
    int i = blockIdx.x * blockDim.x + threadIdx.x;
    if (i < KK1 * CC * CC) {
        int kk = i >> 7, n = i & 127;
        float v = W1[i];
        __nv_bfloat16 h = __float2bfloat16(v);
        g_Whi1[(size_t)n * (KK1 * CC) + kk] = h;
        g_Wlo1[(size_t)n * (KK1 * CC) + kk] = __float2bfloat16(v - __bfloat162float(h));
    }
    if (i < KK2 * CC * CC) {
        int kk = i >> 7, n = i & 127;
        float v = (n < OUTC) ? W2[(size_t)kk * OUTC + n]
                             : W3[(size_t)kk * OUTC + (n - OUTC)];
        __nv_bfloat16 h = __float2bfloat16(v);
        g_Whi23[(size_t)n * (KK2 * CC) + kk] = h;
        g_Wlo23[(size_t)n * (KK2 * CC) + kk] = __float2bfloat16(v - __bfloat162float(h));
    }
}

// ---------------- mma.sync GEMM: g_acc = T @ W (3-term bf16 split) ----------------
#define ROWB   80                  // smem row stride bytes (32 bf16 + 16B pad)
#define TILE_B (128 * ROWB)        // 10240 per tile

__device__ __forceinline__ uint32_t pack2(float a, float b) {
    __nv_bfloat162 t = __floats2bfloat162_rn(a, b);
    return *reinterpret_cast<uint32_t*>(&t);
}
__device__ __forceinline__ float resid(float v) {
    return v - __bfloat162float(__float2bfloat16(v));
}

__global__ __launch_bounds__(256) void k_mm(int which, const float* __restrict__ A0) {
    __shared__ __align__(16) char smem[4 * TILE_B];   // Ah | Al | Bh | Bl
    const __nv_bfloat16* __restrict__ Bhi = which ? g_Whi23 : g_Whi1;
    const __nv_bfloat16* __restrict__ Blo = which ? g_Wlo23 : g_Wlo1;
    const int Ktot = which ? (KK2 * CC) : (KK1 * CC);

    const uint32_t sm = smem_u32(smem);
    const uint32_t Ah = sm, Al = sm + TILE_B, Bh = sm + 2 * TILE_B, Bl = sm + 3 * TILE_B;
    const int tid = threadIdx.x;
    const int lane = tid & 31;
    const int w = tid >> 5;
    const int wm = w & 3;
    const int wn = w >> 2;
    const int m0 = blockIdx.x * 128;
    const int NCH = Ktot >> 5;

    const int cr = tid >> 1;
    const int cs = tid & 1;
    const int arow = m0 + cr;

    uint4 ah2[2], al2[2], bh2[2], bl2[2];

    auto load_regs = [&](int c) {
        int blk = c >> 2;
        const float* abase = (blk == 0 && A0 != nullptr)
                             ? A0 : (g_T + (size_t)blk * NN * CC);
        float4 fa[4];
        if (arow < NN) {
            const float4* pa = (const float4*)(abase + (size_t)arow * CC + (c & 3) * 32 + cs * 16);
#pragma unroll
            for (int i = 0; i < 4; i++) fa[i] = pa[i];
        } else {
#pragma unroll
            for (int i = 0; i < 4; i++) fa[i] = make_float4(0.f, 0.f, 0.f, 0.f);
        }
#pragma unroll
        for (int i = 0; i < 2; i++) {
            float4 f0 = fa[2 * i], f1 = fa[2 * i + 1];
            ah2[i] = make_uint4(pack2(f0.x, f0.y), pack2(f0.z, f0.w),
                                pack2(f1.x, f1.y), pack2(f1.z, f1.w));
            al2[i] = make_uint4(pack2(resid(f0.x), resid(f0.y)),
                                pack2(resid(f0.z), resid(f0.w)),
                                pack2(resid(f1.x), resid(f1.y)),
                                pack2(resid(f1.z), resid(f1.w)));
        }
        size_t gb = (size_t)cr * Ktot + c * 32 + cs * 16;
        const uint4* pw = (const uint4*)(Bhi + gb);
        const uint4* pl = (const uint4*)(Blo + gb);
        bh2[0] = pw[0]; bh2[1] = pw[1];
        bl2[0] = pl[0]; bl2[1] = pl[1];
    };

    float acc[2][8][4];
#pragma unroll
    for (int i = 0; i < 2; i++)
#pragma unroll
        for (int j = 0; j < 8; j++)
#pragma unroll
            for (int q = 0; q < 4; q++) acc[i][j][q] = 0.f;

    const uint32_t a_row = wm * 32 + (lane & 15);
    const uint32_t a_k8  = (lane >> 4) << 3;
    const uint32_t b_row = wn * 64 + ((lane >> 4) << 3) + (lane & 7);
    const uint32_t b_k8  = ((lane >> 3) & 1) << 3;
    const uint32_t soff = (uint32_t)(cr * ROWB + cs * 32);

    load_regs(0);
    {
        *(uint4*)(smem + 0 * TILE_B + soff)      = ah2[0];
        *(uint4*)(smem + 0 * TILE_B + soff + 16) = ah2[1];
        *(uint4*)(smem + 1 * TILE_B + soff)      = al2[0];
        *(uint4*)(smem + 1 * TILE_B + soff + 16) = al2[1];
        *(uint4*)(smem + 2 * TILE_B + soff)      = bh2[0];
        *(uint4*)(smem + 2 * TILE_B + soff + 16) = bh2[1];
        *(uint4*)(smem + 3 * TILE_B + soff)      = bl2[0];
        *(uint4*)(smem + 3 * TILE_B + soff + 16) = bl2[1];
    }
    __syncthreads();

    for (int c = 0; c < NCH; c++) {
        if (c + 1 < NCH) load_regs(c + 1);

#pragma unroll
        for (int ks = 0; ks < 2; ks++) {
            const uint32_t k0 = ks * 16;
            uint32_t ahf[2][4], alf[2][4];
#pragma unroll
            for (int mt = 0; mt < 2; mt++) {
                uint32_t addr = Ah + (a_row + mt * 16) * ROWB + (k0 + a_k8) * 2;
                LDSM_X4(ahf[mt][0], ahf[mt][1], ahf[mt][2], ahf[mt][3], addr);
                addr = Al + (a_row + mt * 16) * ROWB + (k0 + a_k8) * 2;
                LDSM_X4(alf[mt][0], alf[mt][1], alf[mt][2], alf[mt][3], addr);
            }
            uint32_t bhf[4][4], blf[4][4];
#pragma unroll
            for (int np = 0; np < 4; np++) {
                uint32_t addr = Bh + (b_row + np * 16) * ROWB + (k0 + b_k8) * 2;
                LDSM_X4(bhf[np][0], bhf[np][1], bhf[np][2], bhf[np][3], addr);
                addr = Bl + (b_row + np * 16) * ROWB + (k0 + b_k8) * 2;
                LDSM_X4(blf[np][0], blf[np][1], blf[np][2], blf[np][3], addr);
            }
#pragma unroll
            for (int mt = 0; mt < 2; mt++) {
#pragma unroll
                for (int np = 0; np < 4; np++) {
                    MMA_BF16(acc[mt][2 * np],     ahf[mt], bhf[np][0], bhf[np][1]);
                    MMA_BF16(acc[mt][2 * np + 1], ahf[mt], bhf[np][2], bhf[np][3]);
                    MMA_BF16(acc[mt][2 * np],     ahf[mt], blf[np][0], blf[np][1]);
                    MMA_BF16(acc[mt][2 * np + 1], ahf[mt], blf[np][2], blf[np][3]);
                    MMA_BF16(acc[mt][2 * np],     alf[mt], bhf[np][0], bhf[np][1]);
                    MMA_BF16(acc[mt][2 * np + 1], alf[mt], bhf[np][2], bhf[np][3]);
                }
            }
        }

        if (c + 1 < NCH) {
            __syncthreads();
            *(uint4*)(smem + 0 * TILE_B + soff)      = ah2[0];
            *(uint4*)(smem + 0 * TILE_B + soff + 16) = ah2[1];
            *(uint4*)(smem + 1 * TILE_B + soff)      = al2[0];
            *(uint4*)(smem + 1 * TILE_B + soff + 16) = al2[1];
            *(uint4*)(smem + 2 * TILE_B + soff)      = bh2[0];
            *(uint4*)(smem + 2 * TILE_B + soff + 16) = bh2[1];
            *(uint4*)(smem + 3 * TILE_B + soff)      = bl2[0];
            *(uint4*)(smem + 3 * TILE_B + soff + 16) = bl2[1];
            __syncthreads();
        }
    }

    const int mw = m0 + wm * 32;
    const int nw = wn * 64;
#pragma unroll
    for (int mt = 0; mt < 2; mt++) {
#pragma unroll
        for (int nt = 0; nt < 8; nt++) {
            int mr = mw + mt * 16 + (lane >> 2);
            int nc = nw + nt * 8 + (lane & 3) * 2;
            if (mr < NN)
                *(float2*)(g_acc + (size_t)mr * CC + nc) =
                    make_float2(acc[mt][nt][0], acc[mt][nt][1]);
            if (mr + 8 < NN)
                *(float2*)(g_acc + (size_t)(mr + 8) * CC + nc) =
                    make_float2(acc[mt][nt][2], acc[mt][nt][3]);
        }
    }
}

// ---------------- BN ----------------
__global__ void k_zero_bn() {
    if (threadIdx.x < CC) { g_bnsum[threadIdx.x] = 0.f; g_bnsq[threadIdx.x] = 0.f; }
}

__global__ void k_bnstat() {
    int c = threadIdx.x;
    float s = 0.f, q = 0.f;
    for (int r = blockIdx.x; r < NN; r += gridDim.x) {
        float v = g_acc[(size_t)r * CC + c];
        s += v; q += v * v;
    }
    atomicAdd(&g_bnsum[c], s);
    atomicAdd(&g_bnsq[c], q);
}

__global__ void k_bnfinal(const float* __restrict__ gA, const float* __restrict__ bA,
                          const float* __restrict__ gB, const float* __restrict__ bB) {
    int c = threadIdx.x;
    if (c >= CC) return;
    float mu = g_bnsum[c] * (1.0f / NN);
    float var = g_bnsq[c] * (1.0f / NN) - mu * mu;
    float gv, bv;
    if (gB != nullptr && c >= OUTC) { gv = gB[c - OUTC]; bv = bB[c - OUTC]; }
    else                            { gv = gA[c];        bv = bA[c]; }
    float sc = rsqrtf(var + EPSF) * gv;
    g_scale[c] = sc;
    g_shift[c] = bv - mu * sc;
}

// BN+ReLU, writing h straight into g_T block 0 (layer-2's T0)
__global__ void k_bnrelu() {
    size_t i = (size_t)blockIdx.x * blockDim.x + threadIdx.x;
    if (i < (size_t)NN * CC) {
        int c = (int)(i & 127);
        float v = g_acc[i] * g_scale[c] + g_shift[c];
        g_T[i] = fmaxf(v, 0.f);
    }
}

__global__ void k_out(float* __restrict__ out) {
    size_t i = (size_t)blockIdx.x * blockDim.x + threadIdx.x;
    if (i < (size_t)NN * CC) {
        int c = (int)(i & 127);
        size_t r = i >> 7;
        float v = g_acc[i] * g_scale[c] + g_shift[c];
        if (c < OUTC) out[r * OUTC + c] = v;
        else          out[(size_t)NN * OUTC + r * OUTC + (c - OUTC)] = v;
    }
}

// ---------------- launcher (single stream, graph-capture safe) ----------------
extern "C" void kernel_launch(void* const* d_in, const int* in_sizes, int n_in,
                              void* d_out, int out_size) {
    const float* x   = (const float*)d_in[0];
    const int*   ei  = (const int*)d_in[1];
    const float* W1  = (const float*)d_in[2];
    const float* g1  = (const float*)d_in[4];
    const float* be1 = (const float*)d_in[5];
    const float* W2  = (const float*)d_in[6];
    const float* g2  = (const float*)d_in[8];
    const float* be2 = (const float*)d_in[9];
    const float* W3  = (const float*)d_in[10];
    const float* g3  = (const float*)d_in[12];
    const float* be3 = (const float*)d_in[13];
    const int* src = ei;
    const int* dst = ei + EE;
    float* out = (float*)d_out;

    const int NB_N = (NN + 255) / 256;
    const int NB_E = (EE + 255) / 256;
    const int NB_PROP = (NN * 32 + 127) / 128;
    const int NB_ELT = (NN * CC + 255) / 256;
    const int NB_MM = (NN + 127) / 128;   // 391

    // graph preprocessing (CSR by dst + packed edge weights) + weight packing
    k_zero_prep<<<NB_N, 256>>>();
    k_packW<<<(KK1 * CC * CC + 255) / 256, 256>>>(W1, W2, W3);
    k_count<<<NB_E, 256>>>(src, dst);
    k_scan1<<<NBLK, 512>>>();
    k_scan2<<<1, 128>>>();
    k_scan3<<<NB_N, 256>>>();
    k_fill<<<NB_E, 256>>>(src, dst);

    // ---- layer 1: Chebyshev K=16 on x (T0 = x read in place) ----
    k_prop<<<NB_PROP, 128>>>(-1, -1, 1, 1.0f, x);        // T1 = P x
    k_prop<<<NB_PROP, 128>>>(1, -2, 2, 2.0f, x);         // T2 = 2 P T1 - x
    for (int k = 3; k < KK1; k++)
        k_prop<<<NB_PROP, 128>>>(k - 1, k - 2, k, 2.0f, x);
    k_mm<<<NB_MM, 256>>>(0, x);                          // block 0 <- x
    k_zero_bn<<<1, 128>>>();
    k_bnstat<<<256, 128>>>();
    k_bnfinal<<<1, 128>>>(g1, be1, nullptr, nullptr);
    k_bnrelu<<<NB_ELT, 256>>>();                         // h -> g_T block 0

    // ---- layers 2+3 share propagations of h (= g_T block 0) ----
    k_prop<<<NB_PROP, 128>>>(0, -1, 1, 1.0f, nullptr);   // T1 = P h
    k_prop<<<NB_PROP, 128>>>(1, 0, 2, 2.0f, nullptr);    // T2 = 2 P T1 - h
    for (int k = 3; k < KK2; k++)
        k_prop<<<NB_PROP, 128>>>(k - 1, k - 2, k, 2.0f, nullptr);
    k_mm<<<NB_MM, 256>>>(1, nullptr);
    k_zero_bn<<<1, 128>>>();
    k_bnstat<<<256, 128>>>();
    k_bnfinal<<<1, 128>>>(g2, be2, g3, be3);
    k_out<<<NB_ELT, 256>>>(out);
}

// round 13
// speedup vs baseline: 1.2873x; 1.0001x over previous
#include <cuda_runtime.h>
#include <cuda_bf16.h>
#include <cstdint>

#define NN   50000
#define EE   800000
#define CC   128
#define OUTC 64
#define KK1  16
#define KK2  8
#define EPSF 1e-5f
#define NBLK 98      // ceil(NN/512)

// ---------------- scratch (device globals; no allocation) ----------------
__device__ float g_dinv[NN];
__device__ int   g_outdeg[NN];
__device__ int   g_indeg[NN];
__device__ int   g_rowptr[NN + 1];
__device__ int   g_fill[NN];
__device__ int2  g_cw[EE];                          // packed (col, w bits)
__device__ float g_T[(size_t)KK1 * NN * CC];        // fp32 Chebyshev blocks; block 0 = h in phase 2
__device__ float g_acc[(size_t)NN * CC];            // GEMM output / pre-BN
__device__ __nv_bfloat16 g_Whi1[CC * (KK1 * CC)];   // [n=128][k=2048]
__device__ __nv_bfloat16 g_Wlo1[CC * (KK1 * CC)];
__device__ __nv_bfloat16 g_Whi23[CC * (KK2 * CC)];  // [n=128][k=1024], packed [W2|W3]
__device__ __nv_bfloat16 g_Wlo23[CC * (KK2 * CC)];
__device__ float g_bnsum[CC];
__device__ float g_bnsq[CC];
__device__ float g_scale[CC];
__device__ float g_shift[CC];
__device__ int   g_bsums[NBLK];

// ---------------- PTX helpers (sm_80+ baseline features only) ----------------
__device__ __forceinline__ uint32_t smem_u32(const void* p) {
    uint32_t a;
    asm("{ .reg .u64 t; cvta.to.shared.u64 t, %1; cvt.u32.u64 %0, t; }" : "=r"(a) : "l"(p));
    return a;
}

#define LDSM_X4(r0, r1, r2, r3, addr)                                     \
    asm volatile("ldmatrix.sync.aligned.m8n8.x4.shared.b16 {%0,%1,%2,%3}, [%4];" \
        : "=r"(r0), "=r"(r1), "=r"(r2), "=r"(r3) : "r"(addr))

#define MMA_BF16(d, a, b0, b1)                                            \
    asm volatile("mma.sync.aligned.m16n8k16.row.col.f32.bf16.bf16.f32 "   \
        "{%0,%1,%2,%3}, {%4,%5,%6,%7}, {%8,%9}, {%0,%1,%2,%3};"           \
        : "+f"((d)[0]), "+f"((d)[1]), "+f"((d)[2]), "+f"((d)[3])          \
        : "r"((a)[0]), "r"((a)[1]), "r"((a)[2]), "r"((a)[3]),             \
          "r"(b0), "r"(b1))

// ---------------- setup kernels ----------------
__global__ void k_zero_prep() {
    int i = blockIdx.x * blockDim.x + threadIdx.x;
    if (i < NN) { g_outdeg[i] = 0; g_indeg[i] = 0; g_fill[i] = 0; }
}

__global__ void k_count(const int* __restrict__ src, const int* __restrict__ dst) {
    int e = blockIdx.x * blockDim.x + threadIdx.x;
    if (e < EE) {
        atomicAdd(&g_outdeg[src[e]], 1);
        atomicAdd(&g_indeg[dst[e]], 1);
    }
}

// scan phase 1 + dinv (both depend only on k_count)
__global__ void k_scan1() {
    __shared__ int s[512];
    int t = threadIdx.x;
    int i = blockIdx.x * 512 + t;
    if (i < NN) {
        int d = g_outdeg[i];
        g_dinv[i] = (d > 0) ? rsqrtf((float)d) : 0.0f;
    }
    int v = (i < NN) ? g_indeg[i] : 0;
    s[t] = v;
    __syncthreads();
    for (int off = 1; off < 512; off <<= 1) {
        int a = (t >= off) ? s[t - off] : 0;
        __syncthreads();
        s[t] += a;
        __syncthreads();
    }
    if (i < NN) g_rowptr[i] = s[t] - v;
    if (t == 511) g_bsums[blockIdx.x] = s[511];
}

__global__ void k_scan2() {
    __shared__ int s[128];
    int t = threadIdx.x;
    int v = (t < NBLK) ? g_bsums[t] : 0;
    s[t] = v;
    __syncthreads();
    for (int off = 1; off < 128; off <<= 1) {
        int a = (t >= off) ? s[t - off] : 0;
        __syncthreads();
        s[t] += a;
        __syncthreads();
    }
    if (t < NBLK) g_bsums[t] = s[t] - v;
}

__global__ void k_scan3() {
    int i = blockIdx.x * blockDim.x + threadIdx.x;
    if (i < NN) g_rowptr[i] += g_bsums[i >> 9];
    if (i == 0) g_rowptr[NN] = EE;
}

__global__ void k_fill(const int* __restrict__ src, const int* __restrict__ dst) {
    int e = blockIdx.x * blockDim.x + threadIdx.x;
    if (e < EE) {
        int s = src[e], d = dst[e];
        int p = g_rowptr[d] + atomicAdd(&g_fill[d], 1);
        float w = -g_dinv[s] * g_dinv[d];
        g_cw[p] = make_int2(s, __float_as_int(w));
    }
}

// ---------------- propagation (dst-CSR SpMM), one warp per node ----------------
__global__ void k_prop(int zk, int subk, int outk, float alpha,
                       const float* __restrict__ xext) {
    int gw = (blockIdx.x * blockDim.x + threadIdx.x) >> 5;
    int lane = threadIdx.x & 31;
    if (gw >= NN) return;
    const float* z = (zk < 0) ? xext : (g_T + (size_t)zk * NN * CC);
    int beg = g_rowptr[gw], end = g_rowptr[gw + 1];
    float4 acc = make_float4(0.f, 0.f, 0.f, 0.f);
    int co = lane << 2;
    int e = beg;
    for (; e + 4 <= end; e += 4) {
        int2 cw0 = __ldg(&g_cw[e]);
        int2 cw1 = __ldg(&g_cw[e + 1]);
        int2 cw2 = __ldg(&g_cw[e + 2]);
        int2 cw3 = __ldg(&g_cw[e + 3]);
        float4 v0 = *(const float4*)(z + (size_t)cw0.x * CC + co);
        float4 v1 = *(const float4*)(z + (size_t)cw1.x * CC + co);
        float4 v2 = *(const float4*)(z + (size_t)cw2.x * CC + co);
        float4 v3 = *(const float4*)(z + (size_t)cw3.x * CC + co);
        float w0 = __int_as_float(cw0.y);
        float w1 = __int_as_float(cw1.y);
        float w2 = __int_as_float(cw2.y);
        float w3 = __int_as_float(cw3.y);
        acc.x += w0 * v0.x; acc.y += w0 * v0.y; acc.z += w0 * v0.z; acc.w += w0 * v0.w;
        acc.x += w1 * v1.x; acc.y += w1 * v1.y; acc.z += w1 * v1.z; acc.w += w1 * v1.w;
        acc.x += w2 * v2.x; acc.y += w2 * v2.y; acc.z += w2 * v2.z; acc.w += w2 * v2.w;
        acc.x += w3 * v3.x; acc.y += w3 * v3.y; acc.z += w3 * v3.z; acc.w += w3 * v3.w;
    }
    for (; e < end; e++) {
        int2 cw = __ldg(&g_cw[e]);
        float4 v = *(const float4*)(z + (size_t)cw.x * CC + co);
        float w = __int_as_float(cw.y);
        acc.x += w * v.x; acc.y += w * v.y;
        acc.z += w * v.z; acc.w += w * v.w;
    }
    size_t o = (size_t)gw * CC + co;
    float4 r;
    if (subk != -1) {
        const float* sp = (subk == -2) ? xext : (g_T + (size_t)subk * NN * CC);
        float4 s = *(const float4*)(sp + o);
        r = make_float4(alpha * acc.x - s.x, alpha * acc.y - s.y,
                        alpha * acc.z - s.z, alpha * acc.w - s.w);
    } else {
        r = make_float4(alpha * acc.x, alpha * acc.y, alpha * acc.z, alpha * acc.w);
    }
    *(float4*)(g_T + (size_t)outk * NN * CC + o) = r;
}

// ---------------- weight pack (fused): fp32 [K][N] -> bf16 hi/lo [N][K] ----------------
__global__ void k_packW(const float* __restrict__ W1, const float* __restrict__ W2,
                        const float* __restrict__ W3) {
    int i = blockIdx.x * blockDim.x + threadIdx.x;
    if (i < KK1 * CC * CC) {
        int kk = i >> 7, n = i & 127;
        float v = W1[i];
        __nv_bfloat16 h = __float2bfloat16(v);
        g_Whi1[(size_t)n * (KK1 * CC) + kk] = h;
        g_Wlo1[(size_t)n * (KK1 * CC) + kk] = __float2bfloat16(v - __bfloat162float(h));
    }
    if (i < KK2 * CC * CC) {
        int kk = i >> 7, n = i & 127;
        float v = (n < OUTC) ? W2[(size_t)kk * OUTC + n]
                             : W3[(size_t)kk * OUTC + (n - OUTC)];
        __nv_bfloat16 h = __float2bfloat16(v);
        g_Whi23[(size_t)n * (KK2 * CC) + kk] = h;
        g_Wlo23[(size_t)n * (KK2 * CC) + kk] = __float2bfloat16(v - __bfloat162float(h));
    }
}

// ---------------- mma.sync GEMM: g_acc = T @ W (3-term bf16 split) ----------------
#define ROWB   80                  // smem row stride bytes (32 bf16 + 16B pad)
#define TILE_B (128 * ROWB)        // 10240 per tile

__device__ __forceinline__ uint32_t pack2(float a, float b) {
    __nv_bfloat162 t = __floats2bfloat162_rn(a, b);
    return *reinterpret_cast<uint32_t*>(&t);
}
__device__ __forceinline__ float resid(float v) {
    return v - __bfloat162float(__float2bfloat16(v));
}

__global__ __launch_bounds__(256) void k_mm(int which, const float* __restrict__ A0) {
    __shared__ __align__(16) char smem[4 * TILE_B];   // Ah | Al | Bh | Bl
    const __nv_bfloat16* __restrict__ Bhi = which ? g_Whi23 : g_Whi1;
    const __nv_bfloat16* __restrict__ Blo = which ? g_Wlo23 : g_Wlo1;
    const int Ktot = which ? (KK2 * CC) : (KK1 * CC);

    const uint32_t sm = smem_u32(smem);
    const uint32_t Ah = sm, Al = sm + TILE_B, Bh = sm + 2 * TILE_B, Bl = sm + 3 * TILE_B;
    const int tid = threadIdx.x;
    const int lane = tid & 31;
    const int w = tid >> 5;
    const int wm = w & 3;
    const int wn = w >> 2;
    const int m0 = blockIdx.x * 128;
    const int NCH = Ktot >> 5;

    const int cr = tid >> 1;
    const int cs = tid & 1;
    const int arow = m0 + cr;

    uint4 ah2[2], al2[2], bh2[2], bl2[2];

    auto load_regs = [&](int c) {
        int blk = c >> 2;
        const float* abase = (blk == 0 && A0 != nullptr)
                             ? A0 : (g_T + (size_t)blk * NN * CC);
        float4 fa[4];
        if (arow < NN) {
            const float4* pa = (const float4*)(abase + (size_t)arow * CC + (c & 3) * 32 + cs * 16);
#pragma unroll
            for (int i = 0; i < 4; i++) fa[i] = pa[i];
        } else {
#pragma unroll
            for (int i = 0; i < 4; i++) fa[i] = make_float4(0.f, 0.f, 0.f, 0.f);
        }
#pragma unroll
        for (int i = 0; i < 2; i++) {
            float4 f0 = fa[2 * i], f1 = fa[2 * i + 1];
            ah2[i] = make_uint4(pack2(f0.x, f0.y), pack2(f0.z, f0.w),
                                pack2(f1.x, f1.y), pack2(f1.z, f1.w));
            al2[i] = make_uint4(pack2(resid(f0.x), resid(f0.y)),
                                pack2(resid(f0.z), resid(f0.w)),
                                pack2(resid(f1.x), resid(f1.y)),
                                pack2(resid(f1.z), resid(f1.w)));
        }
        size_t gb = (size_t)cr * Ktot + c * 32 + cs * 16;
        const uint4* pw = (const uint4*)(Bhi + gb);
        const uint4* pl = (const uint4*)(Blo + gb);
        bh2[0] = pw[0]; bh2[1] = pw[1];
        bl2[0] = pl[0]; bl2[1] = pl[1];
    };

    float acc[2][8][4];
#pragma unroll
    for (int i = 0; i < 2; i++)
#pragma unroll
        for (int j = 0; j < 8; j++)
#pragma unroll
            for (int q = 0; q < 4; q++) acc[i][j][q] = 0.f;

    const uint32_t a_row = wm * 32 + (lane & 15);
    const uint32_t a_k8  = (lane >> 4) << 3;
    const uint32_t b_row = wn * 64 + ((lane >> 4) << 3) + (lane & 7);
    const uint32_t b_k8  = ((lane >> 3) & 1) << 3;
    const uint32_t soff = (uint32_t)(cr * ROWB + cs * 32);

    load_regs(0);
    {
        *(uint4*)(smem + 0 * TILE_B + soff)      = ah2[0];
        *(uint4*)(smem + 0 * TILE_B + soff + 16) = ah2[1];
        *(uint4*)(smem + 1 * TILE_B + soff)      = al2[0];
        *(uint4*)(smem + 1 * TILE_B + soff + 16) = al2[1];
        *(uint4*)(smem + 2 * TILE_B + soff)      = bh2[0];
        *(uint4*)(smem + 2 * TILE_B + soff + 16) = bh2[1];
        *(uint4*)(smem + 3 * TILE_B + soff)      = bl2[0];
        *(uint4*)(smem + 3 * TILE_B + soff + 16) = bl2[1];
    }
    __syncthreads();

    for (int c = 0; c < NCH; c++) {
        if (c + 1 < NCH) load_regs(c + 1);

#pragma unroll
        for (int ks = 0; ks < 2; ks++) {
            const uint32_t k0 = ks * 16;
            uint32_t ahf[2][4], alf[2][4];
#pragma unroll
            for (int mt = 0; mt < 2; mt++) {
                uint32_t addr = Ah + (a_row + mt * 16) * ROWB + (k0 + a_k8) * 2;
                LDSM_X4(ahf[mt][0], ahf[mt][1], ahf[mt][2], ahf[mt][3], addr);
                addr = Al + (a_row + mt * 16) * ROWB + (k0 + a_k8) * 2;
                LDSM_X4(alf[mt][0], alf[mt][1], alf[mt][2], alf[mt][3], addr);
            }
            uint32_t bhf[4][4], blf[4][4];
#pragma unroll
            for (int np = 0; np < 4; np++) {
                uint32_t addr = Bh + (b_row + np * 16) * ROWB + (k0 + b_k8) * 2;
                LDSM_X4(bhf[np][0], bhf[np][1], bhf[np][2], bhf[np][3], addr);
                addr = Bl + (b_row + np * 16) * ROWB + (k0 + b_k8) * 2;
                LDSM_X4(blf[np][0], blf[np][1], blf[np][2], blf[np][3], addr);
            }
#pragma unroll
            for (int mt = 0; mt < 2; mt++) {
#pragma unroll
                for (int np = 0; np < 4; np++) {
                    MMA_BF16(acc[mt][2 * np],     ahf[mt], bhf[np][0], bhf[np][1]);
                    MMA_BF16(acc[mt][2 * np + 1], ahf[mt], bhf[np][2], bhf[np][3]);
                    MMA_BF16(acc[mt][2 * np],     ahf[mt], blf[np][0], blf[np][1]);
                    MMA_BF16(acc[mt][2 * np + 1], ahf[mt], blf[np][2], blf[np][3]);
                    MMA_BF16(acc[mt][2 * np],     alf[mt], bhf[np][0], bhf[np][1]);
                    MMA_BF16(acc[mt][2 * np + 1], alf[mt], bhf[np][2], bhf[np][3]);
                }
            }
        }

        if (c + 1 < NCH) {
            __syncthreads();
            *(uint4*)(smem + 0 * TILE_B + soff)      = ah2[0];
            *(uint4*)(smem + 0 * TILE_B + soff + 16) = ah2[1];
            *(uint4*)(smem + 1 * TILE_B + soff)      = al2[0];
            *(uint4*)(smem + 1 * TILE_B + soff + 16) = al2[1];
            *(uint4*)(smem + 2 * TILE_B + soff)      = bh2[0];
            *(uint4*)(smem + 2 * TILE_B + soff + 16) = bh2[1];
            *(uint4*)(smem + 3 * TILE_B + soff)      = bl2[0];
            *(uint4*)(smem + 3 * TILE_B + soff + 16) = bl2[1];
            __syncthreads();
        }
    }

    const int mw = m0 + wm * 32;
    const int nw = wn * 64;
#pragma unroll
    for (int mt = 0; mt < 2; mt++) {
#pragma unroll
        for (int nt = 0; nt < 8; nt++) {
            int mr = mw + mt * 16 + (lane >> 2);
            int nc = nw + nt * 8 + (lane & 3) * 2;
            if (mr < NN)
                *(float2*)(g_acc + (size_t)mr * CC + nc) =
                    make_float2(acc[mt][nt][0], acc[mt][nt][1]);
            if (mr + 8 < NN)
                *(float2*)(g_acc + (size_t)(mr + 8) * CC + nc) =
                    make_float2(acc[mt][nt][2], acc[mt][nt][3]);
        }
    }
}

// ---------------- BN ----------------
__global__ void k_zero_bn() {
    if (threadIdx.x < CC) { g_bnsum[threadIdx.x] = 0.f; g_bnsq[threadIdx.x] = 0.f; }
}

__global__ void k_bnstat() {
    int c = threadIdx.x;
    float s = 0.f, q = 0.f;
    for (int r = blockIdx.x; r < NN; r += gridDim.x) {
        float v = g_acc[(size_t)r * CC + c];
        s += v; q += v * v;
    }
    atomicAdd(&g_bnsum[c], s);
    atomicAdd(&g_bnsq[c], q);
}

// consumes g_bnsum/g_bnsq, then re-zeroes them for the NEXT use WITHIN this call
// (the launcher still runs k_zero_bn before the first k_bnstat of every call).
__global__ void k_bnfinal(const float* __restrict__ gA, const float* __restrict__ bA,
                          const float* __restrict__ gB, const float* __restrict__ bB) {
    int c = threadIdx.x;
    if (c >= CC) return;
    float mu = g_bnsum[c] * (1.0f / NN);
    float var = g_bnsq[c] * (1.0f / NN) - mu * mu;
    g_bnsum[c] = 0.f;
    g_bnsq[c] = 0.f;
    float gv, bv;
    if (gB != nullptr && c >= OUTC) { gv = gB[c - OUTC]; bv = bB[c - OUTC]; }
    else                            { gv = gA[c];        bv = bA[c]; }
    float sc = rsqrtf(var + EPSF) * gv;
    g_scale[c] = sc;
    g_shift[c] = bv - mu * sc;
}

// BN+ReLU, writing h straight into g_T block 0 (layer-2's T0)
__global__ void k_bnrelu() {
    size_t i = (size_t)blockIdx.x * blockDim.x + threadIdx.x;
    if (i < (size_t)NN * CC) {
        int c = (int)(i & 127);
        float v = g_acc[i] * g_scale[c] + g_shift[c];
        g_T[i] = fmaxf(v, 0.f);
    }
}

__global__ void k_out(float* __restrict__ out) {
    size_t i = (size_t)blockIdx.x * blockDim.x + threadIdx.x;
    if (i < (size_t)NN * CC) {
        int c = (int)(i & 127);
        size_t r = i >> 7;
        float v = g_acc[i] * g_scale[c] + g_shift[c];
        if (c < OUTC) out[r * OUTC + c] = v;
        else          out[(size_t)NN * OUTC + r * OUTC + (c - OUTC)] = v;
    }
}

// ---------------- launcher (single stream, graph-capture safe) ----------------
extern "C" void kernel_launch(void* const* d_in, const int* in_sizes, int n_in,
                              void* d_out, int out_size) {
    const float* x   = (const float*)d_in[0];
    const int*   ei  = (const int*)d_in[1];
    const float* W1  = (const float*)d_in[2];
    const float* g1  = (const float*)d_in[4];
    const float* be1 = (const float*)d_in[5];
    const float* W2  = (const float*)d_in[6];
    const float* g2  = (const float*)d_in[8];
    const float* be2 = (const float*)d_in[9];
    const float* W3  = (const float*)d_in[10];
    const float* g3  = (const float*)d_in[12];
    const float* be3 = (const float*)d_in[13];
    const int* src = ei;
    const int* dst = ei + EE;
    float* out = (float*)d_out;

    const int NB_N = (NN + 255) / 256;
    const int NB_E = (EE + 255) / 256;
    const int NB_PROP = (NN * 32 + 127) / 128;
    const int NB_ELT = (NN * CC + 255) / 256;
    const int NB_MM = (NN + 127) / 128;   // 391

    // graph preprocessing (CSR by dst + packed edge weights) + weight packing
    k_zero_prep<<<NB_N, 256>>>();
    k_packW<<<(KK1 * CC * CC + 255) / 256, 256>>>(W1, W2, W3);
    k_count<<<NB_E, 256>>>(src, dst);
    k_scan1<<<NBLK, 512>>>();
    k_scan2<<<1, 128>>>();
    k_scan3<<<NB_N, 256>>>();
    k_fill<<<NB_E, 256>>>(src, dst);

    // ---- layer 1: Chebyshev K=16 on x (T0 = x read in place) ----
    k_prop<<<NB_PROP, 128>>>(-1, -1, 1, 1.0f, x);        // T1 = P x
    k_prop<<<NB_PROP, 128>>>(1, -2, 2, 2.0f, x);         // T2 = 2 P T1 - x
    for (int k = 3; k < KK1; k++)
        k_prop<<<NB_PROP, 128>>>(k - 1, k - 2, k, 2.0f, x);
    k_mm<<<NB_MM, 256>>>(0, x);                          // block 0 <- x
    k_zero_bn<<<1, 128>>>();
    k_bnstat<<<256, 128>>>();
    k_bnfinal<<<1, 128>>>(g1, be1, nullptr, nullptr);    // also re-zeroes sums
    k_bnrelu<<<NB_ELT, 256>>>();                         // h -> g_T block 0

    // ---- layers 2+3 share propagations of h (= g_T block 0) ----
    k_prop<<<NB_PROP, 128>>>(0, -1, 1, 1.0f, nullptr);   // T1 = P h
    k_prop<<<NB_PROP, 128>>>(1, 0, 2, 2.0f, nullptr);    // T2 = 2 P T1 - h
    for (int k = 3; k < KK2; k++)
        k_prop<<<NB_PROP, 128>>>(k - 1, k - 2, k, 2.0f, nullptr);
    k_mm<<<NB_MM, 256>>>(1, nullptr);
    k_bnstat<<<256, 128>>>();                            // sums were re-zeroed by bnfinal
    k_bnfinal<<<1, 128>>>(g2, be2, g3, be3);
    k_out<<<NB_ELT, 256>>>(out);
}

// round 14
// speedup vs baseline: 1.4092x; 1.0947x over previous
#include <cuda_runtime.h>
#include <cuda_bf16.h>
#include <cstdint>

#define NN   50000
#define EE   800000
#define CC   128
#define OUTC 64
#define KK1  16
#define KK2  8
#define EPSF 1e-5f
#define NBLK 98      // ceil(NN/512)

// ---------------- scratch (device globals; no allocation) ----------------
__device__ float g_dinv[NN];
__device__ int   g_outdeg[NN];
__device__ int   g_indeg[NN];
__device__ int   g_rowptr[NN + 1];
__device__ int   g_fill[NN];
__device__ int2  g_cw[EE];                          // packed (col, w bits)
__device__ float g_T[(size_t)KK1 * NN * CC];        // fp32 Chebyshev blocks; block 0 = h in phase 2
__device__ float g_acc[(size_t)NN * CC];            // GEMM output / pre-BN
__device__ __nv_bfloat16 g_Whi1[CC * (KK1 * CC)];   // [n=128][k=2048]
__device__ __nv_bfloat16 g_Wlo1[CC * (KK1 * CC)];
__device__ __nv_bfloat16 g_Whi23[CC * (KK2 * CC)];  // [n=128][k=1024], packed [W2|W3]
__device__ __nv_bfloat16 g_Wlo23[CC * (KK2 * CC)];
__device__ float g_bnsum[CC];
__device__ float g_bnsq[CC];
__device__ float g_scale[CC];
__device__ float g_shift[CC];
__device__ int   g_bsums[NBLK];

// ---------------- PTX helpers (sm_80+ baseline features only) ----------------
__device__ __forceinline__ uint32_t smem_u32(const void* p) {
    uint32_t a;
    asm("{ .reg .u64 t; cvta.to.shared.u64 t, %1; cvt.u32.u64 %0, t; }" : "=r"(a) : "l"(p));
    return a;
}

#define LDSM_X4(r0, r1, r2, r3, addr)                                     \
    asm volatile("ldmatrix.sync.aligned.m8n8.x4.shared.b16 {%0,%1,%2,%3}, [%4];" \
        : "=r"(r0), "=r"(r1), "=r"(r2), "=r"(r3) : "r"(addr))

#define MMA_BF16(d, a, b0, b1)                                            \
    asm volatile("mma.sync.aligned.m16n8k16.row.col.f32.bf16.bf16.f32 "   \
        "{%0,%1,%2,%3}, {%4,%5,%6,%7}, {%8,%9}, {%0,%1,%2,%3};"           \
        : "+f"((d)[0]), "+f"((d)[1]), "+f"((d)[2]), "+f"((d)[3])          \
        : "r"((a)[0]), "r"((a)[1]), "r"((a)[2]), "r"((a)[3]),             \
          "r"(b0), "r"(b1))

// ---------------- setup kernels ----------------
__global__ void k_zero_prep() {
    int i = blockIdx.x * blockDim.x + threadIdx.x;
    if (i < NN) { g_outdeg[i] = 0; g_indeg[i] = 0; g_fill[i] = 0; }
}

__global__ void k_count(const int* __restrict__ src, const int* __restrict__ dst) {
    int e = blockIdx.x * blockDim.x + threadIdx.x;
    if (e < EE) {
        atomicAdd(&g_outdeg[src[e]], 1);
        atomicAdd(&g_indeg[dst[e]], 1);
    }
}

// scan phase 1 + dinv (both depend only on k_count)
__global__ void k_scan1() {
    __shared__ int s[512];
    int t = threadIdx.x;
    int i = blockIdx.x * 512 + t;
    if (i < NN) {
        int d = g_outdeg[i];
        g_dinv[i] = (d > 0) ? rsqrtf((float)d) : 0.0f;
    }
    int v = (i < NN) ? g_indeg[i] : 0;
    s[t] = v;
    __syncthreads();
    for (int off = 1; off < 512; off <<= 1) {
        int a = (t >= off) ? s[t - off] : 0;
        __syncthreads();
        s[t] += a;
        __syncthreads();
    }
    if (i < NN) g_rowptr[i] = s[t] - v;
    if (t == 511) g_bsums[blockIdx.x] = s[511];
}

__global__ void k_scan2() {
    __shared__ int s[128];
    int t = threadIdx.x;
    int v = (t < NBLK) ? g_bsums[t] : 0;
    s[t] = v;
    __syncthreads();
    for (int off = 1; off < 128; off <<= 1) {
        int a = (t >= off) ? s[t - off] : 0;
        __syncthreads();
        s[t] += a;
        __syncthreads();
    }
    if (t < NBLK) g_bsums[t] = s[t] - v;
}

__global__ void k_scan3() {
    int i = blockIdx.x * blockDim.x + threadIdx.x;
    if (i < NN) g_rowptr[i] += g_bsums[i >> 9];
    if (i == 0) g_rowptr[NN] = EE;
}

__global__ void k_fill(const int* __restrict__ src, const int* __restrict__ dst) {
    int e = blockIdx.x * blockDim.x + threadIdx.x;
    if (e < EE) {
        int s = src[e], d = dst[e];
        int p = g_rowptr[d] + atomicAdd(&g_fill[d], 1);
        float w = -g_dinv[s] * g_dinv[d];
        g_cw[p] = make_int2(s, __float_as_int(w));
    }
}

// ---------------- propagation (dst-CSR SpMM), one warp per node ----------------
__global__ void k_prop(int zk, int subk, int outk, float alpha,
                       const float* __restrict__ xext) {
    int gw = (blockIdx.x * blockDim.x + threadIdx.x) >> 5;
    int lane = threadIdx.x & 31;
    if (gw >= NN) return;
    const float* z = (zk < 0) ? xext : (g_T + (size_t)zk * NN * CC);
    int beg = g_rowptr[gw], end = g_rowptr[gw + 1];
    float4 acc = make_float4(0.f, 0.f, 0.f, 0.f);
    int co = lane << 2;
    int e = beg;
    for (; e + 4 <= end; e += 4) {
        int2 cw0 = __ldg(&g_cw[e]);
        int2 cw1 = __ldg(&g_cw[e + 1]);
        int2 cw2 = __ldg(&g_cw[e + 2]);
        int2 cw3 = __ldg(&g_cw[e + 3]);
        float4 v0 = *(const float4*)(z + (size_t)cw0.x * CC + co);
        float4 v1 = *(const float4*)(z + (size_t)cw1.x * CC + co);
        float4 v2 = *(const float4*)(z + (size_t)cw2.x * CC + co);
        float4 v3 = *(const float4*)(z + (size_t)cw3.x * CC + co);
        float w0 = __int_as_float(cw0.y);
        float w1 = __int_as_float(cw1.y);
        float w2 = __int_as_float(cw2.y);
        float w3 = __int_as_float(cw3.y);
        acc.x += w0 * v0.x; acc.y += w0 * v0.y; acc.z += w0 * v0.z; acc.w += w0 * v0.w;
        acc.x += w1 * v1.x; acc.y += w1 * v1.y; acc.z += w1 * v1.z; acc.w += w1 * v1.w;
        acc.x += w2 * v2.x; acc.y += w2 * v2.y; acc.z += w2 * v2.z; acc.w += w2 * v2.w;
        acc.x += w3 * v3.x; acc.y += w3 * v3.y; acc.z += w3 * v3.z; acc.w += w3 * v3.w;
    }
    for (; e < end; e++) {
        int2 cw = __ldg(&g_cw[e]);
        float4 v = *(const float4*)(z + (size_t)cw.x * CC + co);
        float w = __int_as_float(cw.y);
        acc.x += w * v.x; acc.y += w * v.y;
        acc.z += w * v.z; acc.w += w * v.w;
    }
    size_t o = (size_t)gw * CC + co;
    float4 r;
    if (subk != -1) {
        const float* sp = (subk == -2) ? xext : (g_T + (size_t)subk * NN * CC);
        float4 s = *(const float4*)(sp + o);
        r = make_float4(alpha * acc.x - s.x, alpha * acc.y - s.y,
                        alpha * acc.z - s.z, alpha * acc.w - s.w);
    } else {
        r = make_float4(alpha * acc.x, alpha * acc.y, alpha * acc.z, alpha * acc.w);
    }
    *(float4*)(g_T + (size_t)outk * NN * CC + o) = r;
}

// ---------------- weight pack (fused): fp32 [K][N] -> bf16 hi/lo [N][K] ----------------
__global__ void k_packW(const float* __restrict__ W1, const float* __restrict__ W2,
                        const float* __restrict__ W3) {
    int i = blockIdx.x * blockDim.x + threadIdx.x;
    if (i < KK1 * CC * CC) {
        int kk = i >> 7, n = i & 127;
        float v = W1[i];
        __nv_bfloat16 h = __float2bfloat16(v);
        g_Whi1[(size_t)n * (KK1 * CC) + kk] = h;
        g_Wlo1[(size_t)n * (KK1 * CC) + kk] = __float2bfloat16(v - __bfloat162float(h));
    }
    if (i < KK2 * CC * CC) {
        int kk = i >> 7, n = i & 127;
        float v = (n < OUTC) ? W2[(size_t)kk * OUTC + n]
                             : W3[(size_t)kk * OUTC + (n - OUTC)];
        __nv_bfloat16 h = __float2bfloat16(v);
        g_Whi23[(size_t)n * (KK2 * CC) + kk] = h;
        g_Wlo23[(size_t)n * (KK2 * CC) + kk] = __float2bfloat16(v - __bfloat162float(h));
    }
}

// ---------------- mma.sync GEMM: g_acc = T @ W (3-term bf16 split) ----------------
// Double-buffered: K-chunks of 16, 2 stages x 24KB (= 48KB static smem),
// one __syncthreads per chunk; STS to the other stage issued before the MMAs.
#define ROWB    48                 // smem row stride bytes (16 bf16 + 16B pad)
#define TILE_B  (128 * ROWB)       // 6144 per buffer
#define STAGE_B (4 * TILE_B)       // 24576 per stage: Ah | Al | Bh | Bl

__device__ __forceinline__ uint32_t pack2(float a, float b) {
    __nv_bfloat162 t = __floats2bfloat162_rn(a, b);
    return *reinterpret_cast<uint32_t*>(&t);
}
__device__ __forceinline__ float resid(float v) {
    return v - __bfloat162float(__float2bfloat16(v));
}

__global__ __launch_bounds__(256) void k_mm(int which, const float* __restrict__ A0) {
    __shared__ __align__(16) char smem[2 * STAGE_B];   // 49152 bytes
    const __nv_bfloat16* __restrict__ Bhi = which ? g_Whi23 : g_Whi1;
    const __nv_bfloat16* __restrict__ Blo = which ? g_Wlo23 : g_Wlo1;
    const int Ktot = which ? (KK2 * CC) : (KK1 * CC);

    const uint32_t sm = smem_u32(smem);
    const int tid = threadIdx.x;
    const int lane = tid & 31;
    const int w = tid >> 5;
    const int wm = w & 3;
    const int wn = w >> 2;
    const int m0 = blockIdx.x * 128;
    const int NCH = Ktot >> 4;                 // 16-wide chunks (128 or 64)

    // copy mapping: row cr = tid>>1 (0..127), half cs = tid&1 (8 elems = 16B)
    const int cr = tid >> 1;
    const int cs = tid & 1;
    const int arow = m0 + cr;

    uint4 ahv, alv, bhv, blv;                  // staged chunk (8 bf16 each)

    auto load_regs = [&](int c) {
        int blk = c >> 3;                      // 8 chunks of 16 per 128-col block
        const float* abase = (blk == 0 && A0 != nullptr)
                             ? A0 : (g_T + (size_t)blk * NN * CC);
        float4 f0, f1;
        if (arow < NN) {
            const float4* pa = (const float4*)(abase + (size_t)arow * CC +
                                               (c & 7) * 16 + cs * 8);
            f0 = pa[0]; f1 = pa[1];
        } else {
            f0 = make_float4(0.f, 0.f, 0.f, 0.f);
            f1 = f0;
        }
        ahv = make_uint4(pack2(f0.x, f0.y), pack2(f0.z, f0.w),
                         pack2(f1.x, f1.y), pack2(f1.z, f1.w));
        alv = make_uint4(pack2(resid(f0.x), resid(f0.y)),
                         pack2(resid(f0.z), resid(f0.w)),
                         pack2(resid(f1.x), resid(f1.y)),
                         pack2(resid(f1.z), resid(f1.w)));
        size_t gb = (size_t)cr * Ktot + c * 16 + cs * 8;
        bhv = *(const uint4*)(Bhi + gb);
        blv = *(const uint4*)(Blo + gb);
    };

    const uint32_t soff = (uint32_t)(cr * ROWB + cs * 16);
    auto sts = [&](int s) {
        char* base = smem + s * STAGE_B;
        *(uint4*)(base + 0 * TILE_B + soff) = ahv;
        *(uint4*)(base + 1 * TILE_B + soff) = alv;
        *(uint4*)(base + 2 * TILE_B + soff) = bhv;
        *(uint4*)(base + 3 * TILE_B + soff) = blv;
    };

    float acc[2][8][4];
#pragma unroll
    for (int i = 0; i < 2; i++)
#pragma unroll
        for (int j = 0; j < 8; j++)
#pragma unroll
            for (int q = 0; q < 4; q++) acc[i][j][q] = 0.f;

    const uint32_t a_row = wm * 32 + (lane & 15);
    const uint32_t a_k8  = (lane >> 4) << 3;
    const uint32_t b_row = wn * 64 + ((lane >> 4) << 3) + (lane & 7);
    const uint32_t b_k8  = ((lane >> 3) & 1) << 3;

    // prologue: chunk 0 -> stage 0; prefetch chunk 1 into regs
    load_regs(0);
    sts(0);
    __syncthreads();
    if (NCH > 1) load_regs(1);

    for (int c = 0; c < NCH; c++) {
        const int s = c & 1;
        if (c + 1 < NCH) sts(s ^ 1);           // store prefetched chunk c+1
        if (c + 2 < NCH) load_regs(c + 2);     // LDGs get a full iteration of cover

        const uint32_t st = sm + s * STAGE_B;
        const uint32_t Ah = st, Al = st + TILE_B, Bh = st + 2 * TILE_B, Bl = st + 3 * TILE_B;

        uint32_t ahf[2][4], alf[2][4];
#pragma unroll
        for (int mt = 0; mt < 2; mt++) {
            uint32_t addr = Ah + (a_row + mt * 16) * ROWB + a_k8 * 2;
            LDSM_X4(ahf[mt][0], ahf[mt][1], ahf[mt][2], ahf[mt][3], addr);
            addr = Al + (a_row + mt * 16) * ROWB + a_k8 * 2;
            LDSM_X4(alf[mt][0], alf[mt][1], alf[mt][2], alf[mt][3], addr);
        }
        uint32_t bhf[4][4], blf[4][4];
#pragma unroll
        for (int np = 0; np < 4; np++) {
            uint32_t addr = Bh + (b_row + np * 16) * ROWB + b_k8 * 2;
            LDSM_X4(bhf[np][0], bhf[np][1], bhf[np][2], bhf[np][3], addr);
            addr = Bl + (b_row + np * 16) * ROWB + b_k8 * 2;
            LDSM_X4(blf[np][0], blf[np][1], blf[np][2], blf[np][3], addr);
        }
#pragma unroll
        for (int mt = 0; mt < 2; mt++) {
#pragma unroll
            for (int np = 0; np < 4; np++) {
                MMA_BF16(acc[mt][2 * np],     ahf[mt], bhf[np][0], bhf[np][1]);
                MMA_BF16(acc[mt][2 * np + 1], ahf[mt], bhf[np][2], bhf[np][3]);
                MMA_BF16(acc[mt][2 * np],     ahf[mt], blf[np][0], blf[np][1]);
                MMA_BF16(acc[mt][2 * np + 1], ahf[mt], blf[np][2], blf[np][3]);
                MMA_BF16(acc[mt][2 * np],     alf[mt], bhf[np][0], bhf[np][1]);
                MMA_BF16(acc[mt][2 * np + 1], alf[mt], bhf[np][2], bhf[np][3]);
            }
        }
        __syncthreads();   // stage s reads done; stage s^1 stores visible
    }

    const int mw = m0 + wm * 32;
    const int nw = wn * 64;
#pragma unroll
    for (int mt = 0; mt < 2; mt++) {
#pragma unroll
        for (int nt = 0; nt < 8; nt++) {
            int mr = mw + mt * 16 + (lane >> 2);
            int nc = nw + nt * 8 + (lane & 3) * 2;
            if (mr < NN)
                *(float2*)(g_acc + (size_t)mr * CC + nc) =
                    make_float2(acc[mt][nt][0], acc[mt][nt][1]);
            if (mr + 8 < NN)
                *(float2*)(g_acc + (size_t)(mr + 8) * CC + nc) =
                    make_float2(acc[mt][nt][2], acc[mt][nt][3]);
        }
    }
}

// ---------------- BN ----------------
__global__ void k_zero_bn() {
    if (threadIdx.x < CC) { g_bnsum[threadIdx.x] = 0.f; g_bnsq[threadIdx.x] = 0.f; }
}

__global__ void k_bnstat() {
    int c = threadIdx.x;
    float s = 0.f, q = 0.f;
    for (int r = blockIdx.x; r < NN; r += gridDim.x) {
        float v = g_acc[(size_t)r * CC + c];
        s += v; q += v * v;
    }
    atomicAdd(&g_bnsum[c], s);
    atomicAdd(&g_bnsq[c], q);
}

// consumes g_bnsum/g_bnsq, then re-zeroes them for the NEXT use WITHIN this call
// (the launcher still runs k_zero_bn before the first k_bnstat of every call).
__global__ void k_bnfinal(const float* __restrict__ gA, const float* __restrict__ bA,
                          const float* __restrict__ gB, const float* __restrict__ bB) {
    int c = threadIdx.x;
    if (c >= CC) return;
    float mu = g_bnsum[c] * (1.0f / NN);
    float var = g_bnsq[c] * (1.0f / NN) - mu * mu;
    g_bnsum[c] = 0.f;
    g_bnsq[c] = 0.f;
    float gv, bv;
    if (gB != nullptr && c >= OUTC) { gv = gB[c - OUTC]; bv = bB[c - OUTC]; }
    else                            { gv = gA[c];        bv = bA[c]; }
    float sc = rsqrtf(var + EPSF) * gv;
    g_scale[c] = sc;
    g_shift[c] = bv - mu * sc;
}

// BN+ReLU, writing h straight into g_T block 0 (layer-2's T0)
__global__ void k_bnrelu() {
    size_t i = (size_t)blockIdx.x * blockDim.x + threadIdx.x;
    if (i < (size_t)NN * CC) {
        int c = (int)(i & 127);
        float v = g_acc[i] * g_scale[c] + g_shift[c];
        g_T[i] = fmaxf(v, 0.f);
    }
}

__global__ void k_out(float* __restrict__ out) {
    size_t i = (size_t)blockIdx.x * blockDim.x + threadIdx.x;
    if (i < (size_t)NN * CC) {
        int c = (int)(i & 127);
        size_t r = i >> 7;
        float v = g_acc[i] * g_scale[c] + g_shift[c];
        if (c < OUTC) out[r * OUTC + c] = v;
        else          out[(size_t)NN * OUTC + r * OUTC + (c - OUTC)] = v;
    }
}

// ---------------- launcher (single stream, graph-capture safe) ----------------
extern "C" void kernel_launch(void* const* d_in, const int* in_sizes, int n_in,
                              void* d_out, int out_size) {
    const float* x   = (const float*)d_in[0];
    const int*   ei  = (const int*)d_in[1];
    const float* W1  = (const float*)d_in[2];
    const float* g1  = (const float*)d_in[4];
    const float* be1 = (const float*)d_in[5];
    const float* W2  = (const float*)d_in[6];
    const float* g2  = (const float*)d_in[8];
    const float* be2 = (const float*)d_in[9];
    const float* W3  = (const float*)d_in[10];
    const float* g3  = (const float*)d_in[12];
    const float* be3 = (const float*)d_in[13];
    const int* src = ei;
    const int* dst = ei + EE;
    float* out = (float*)d_out;

    const int NB_N = (NN + 255) / 256;
    const int NB_E = (EE + 255) / 256;
    const int NB_PROP = (NN * 32 + 127) / 128;
    const int NB_ELT = (NN * CC + 255) / 256;
    const int NB_MM = (NN + 127) / 128;   // 391

    // graph preprocessing (CSR by dst + packed edge weights) + weight packing
    k_zero_prep<<<NB_N, 256>>>();
    k_packW<<<(KK1 * CC * CC + 255) / 256, 256>>>(W1, W2, W3);
    k_count<<<NB_E, 256>>>(src, dst);
    k_scan1<<<NBLK, 512>>>();
    k_scan2<<<1, 128>>>();
    k_scan3<<<NB_N, 256>>>();
    k_fill<<<NB_E, 256>>>(src, dst);

    // ---- layer 1: Chebyshev K=16 on x (T0 = x read in place) ----
    k_prop<<<NB_PROP, 128>>>(-1, -1, 1, 1.0f, x);        // T1 = P x
    k_prop<<<NB_PROP, 128>>>(1, -2, 2, 2.0f, x);         // T2 = 2 P T1 - x
    for (int k = 3; k < KK1; k++)
        k_prop<<<NB_PROP, 128>>>(k - 1, k - 2, k, 2.0f, x);
    k_mm<<<NB_MM, 256>>>(0, x);                          // block 0 <- x
    k_zero_bn<<<1, 128>>>();
    k_bnstat<<<256, 128>>>();
    k_bnfinal<<<1, 128>>>(g1, be1, nullptr, nullptr);    // also re-zeroes sums
    k_bnrelu<<<NB_ELT, 256>>>();                         // h -> g_T block 0

    // ---- layers 2+3 share propagations of h (= g_T block 0) ----
    k_prop<<<NB_PROP, 128>>>(0, -1, 1, 1.0f, nullptr);   // T1 = P h
    k_prop<<<NB_PROP, 128>>>(1, 0, 2, 2.0f, nullptr);    // T2 = 2 P T1 - h
    for (int k = 3; k < KK2; k++)
        k_prop<<<NB_PROP, 128>>>(k - 1, k - 2, k, 2.0f, nullptr);
    k_mm<<<NB_MM, 256>>>(1, nullptr);
    k_bnstat<<<256, 128>>>();                            // sums were re-zeroed by bnfinal
    k_bnfinal<<<1, 128>>>(g2, be2, g3, be3);
    k_out<<<NB_ELT, 256>>>(out);
}